// round 2
// baseline (speedup 1.0000x reference)
#include <cuda_runtime.h>
#include <cstdint>
#include <math.h>

// Problem constants
#define B 128
#define T 20
#define VV 10000
#define H 512
#define F 49
// derived
#define H2 1024   // 2H
#define H4 2048   // 4H
#define K3 1536   // 3H (emb | gf | h)
#define HF 25088  // H*F

// ---------------- scratch (device globals; no allocation allowed) ----------
__device__ float g_Vproj[B * F * H];        // [B,F,H]  12.8 MB
__device__ float g_X[T * B * H2];           // [T,B,2H] rows t*B+b: [h | attended]
__device__ float g_gates[B * H4];
__device__ float g_h[B * H];
__device__ float g_c[B * H];
__device__ float g_hw[B * H];
__device__ float g_bias[H4];

// ---------------- prep: bias = b_ih + b_hh ; h,c <- h0,c0 -------------------
__global__ void prep_kernel(const float* __restrict__ h0, const float* __restrict__ c0,
                            const float* __restrict__ bih, const float* __restrict__ bhh)
{
    int idx = blockIdx.x * blockDim.x + threadIdx.x;   // 65536
    g_h[idx] = h0[idx];
    g_c[idx] = c0[idx];
    if (idx < H4) g_bias[idx] = bih[idx] + bhh[idx];
}

// ---------------- Vproj = swap(area) @ Wv : [6272,512] @ [512,512] ----------
// A[m][k] = area[(m/49)*HF + k*49 + (m%49)]
__global__ void vproj_kernel(const float* __restrict__ area, const float* __restrict__ Wv)
{
    __shared__ float As[16][66];
    __shared__ float Bs[16][66];
    int tid = threadIdx.x;                 // 256
    int n0 = blockIdx.x * 64;              // 8 blocks
    int m0 = blockIdx.y * 64;              // 98 blocks
    int tm = (tid >> 4) * 4;
    int tn = (tid & 15) * 4;
    float acc[4][4] = {};
    for (int k0 = 0; k0 < H; k0 += 16) {
        #pragma unroll
        for (int i = 0; i < 4; i++) {
            int idx = tid + i * 256;       // 0..1023
            int kk = idx >> 6, mm = idx & 63;
            int m = m0 + mm;
            int bb = m / 49, ff = m % 49;
            As[kk][mm] = area[(size_t)bb * HF + (size_t)(k0 + kk) * 49 + ff];
        }
        #pragma unroll
        for (int i = 0; i < 4; i++) {
            int idx = tid + i * 256;
            int kk = idx >> 6, nn = idx & 63;
            Bs[kk][nn] = Wv[(size_t)(k0 + kk) * H + n0 + nn];
        }
        __syncthreads();
        #pragma unroll
        for (int k = 0; k < 16; k++) {
            float a[4], bb2[4];
            #pragma unroll
            for (int i = 0; i < 4; i++) a[i] = As[k][tm + i];
            #pragma unroll
            for (int j = 0; j < 4; j++) bb2[j] = Bs[k][tn + j];
            #pragma unroll
            for (int i = 0; i < 4; i++)
                #pragma unroll
                for (int j = 0; j < 4; j++)
                    acc[i][j] += a[i] * bb2[j];
        }
        __syncthreads();
    }
    #pragma unroll
    for (int i = 0; i < 4; i++)
        #pragma unroll
        for (int j = 0; j < 4; j++)
            g_Vproj[(size_t)(m0 + tm + i) * H + n0 + tn + j] = acc[i][j];
}

// ---------------- gates = [emb|gf|h] @ [W_ih;W_hh] + bias : [128,2048] ------
__global__ void gates_kernel(const int* __restrict__ cap, const float* __restrict__ gf,
                             const float* __restrict__ emb, const float* __restrict__ Wih,
                             const float* __restrict__ Whh, int t)
{
    __shared__ float As[16][34];
    __shared__ float Bs[16][66];
    __shared__ int stok[32];
    int tid = threadIdx.x;                 // 256
    int n0 = blockIdx.x * 64;              // 32 blocks
    int m0 = blockIdx.y * 32;              // 4 blocks
    if (tid < 32) stok[tid] = cap[(m0 + tid) * T + t];
    __syncthreads();
    int tm = (tid >> 4) * 2;
    int tn = (tid & 15) * 4;
    float acc[2][4] = {};
    for (int k0 = 0; k0 < K3; k0 += 16) {
        #pragma unroll
        for (int i = 0; i < 2; i++) {
            int idx = tid + i * 256;       // 0..511
            int mm = idx >> 4, kk = idx & 15;
            int m = m0 + mm, k = k0 + kk;
            float v;
            if (k < 512)        v = emb[(size_t)stok[mm] * H + k];
            else if (k < 1024)  v = gf[(size_t)m * H + (k - 512)];
            else                v = g_h[(size_t)m * H + (k - 1024)];
            As[kk][mm] = v;
        }
        #pragma unroll
        for (int i = 0; i < 4; i++) {
            int idx = tid + i * 256;       // 0..1023
            int kk = idx >> 6, nn = idx & 63;
            int k = k0 + kk, n = n0 + nn;
            Bs[kk][nn] = (k < 1024) ? Wih[(size_t)k * H4 + n]
                                    : Whh[(size_t)(k - 1024) * H4 + n];
        }
        __syncthreads();
        #pragma unroll
        for (int k = 0; k < 16; k++) {
            float a0 = As[k][tm], a1 = As[k][tm + 1];
            float b0 = Bs[k][tn], b1 = Bs[k][tn + 1];
            float b2 = Bs[k][tn + 2], b3 = Bs[k][tn + 3];
            acc[0][0] += a0 * b0; acc[0][1] += a0 * b1;
            acc[0][2] += a0 * b2; acc[0][3] += a0 * b3;
            acc[1][0] += a1 * b0; acc[1][1] += a1 * b1;
            acc[1][2] += a1 * b2; acc[1][3] += a1 * b3;
        }
        __syncthreads();
    }
    #pragma unroll
    for (int i = 0; i < 2; i++)
        #pragma unroll
        for (int j = 0; j < 4; j++)
            g_gates[(size_t)(m0 + tm + i) * H4 + n0 + tn + j] =
                acc[i][j] + g_bias[n0 + tn + j];
}

// ---------------- LSTM elementwise; also writes h into X --------------------
__global__ void lstm_kernel(int t)
{
    int idx = blockIdx.x * blockDim.x + threadIdx.x;   // 65536
    int bb = idx >> 9, hh = idx & 511;
    const float* g = g_gates + (size_t)bb * H4;
    float gi = g[hh], gfv = g[512 + hh], gg = g[1024 + hh], go = g[1536 + hh];
    float si = 1.f / (1.f + expf(-gi));
    float sf = 1.f / (1.f + expf(-gfv));
    float so = 1.f / (1.f + expf(-go));
    float c = sf * g_c[idx] + si * tanhf(gg);
    float h = so * tanhf(c);
    g_c[idx] = c;
    g_h[idx] = h;
    g_X[((size_t)t * B + bb) * H2 + hh] = h;
}

// ---------------- hw = h @ Wh : [128,512] @ [512,512] -----------------------
__global__ void hw_kernel(const float* __restrict__ Wh)
{
    __shared__ float As[16][18];           // [m][k]
    __shared__ float Bs[16][66];           // [k][n]
    int tid = threadIdx.x;                 // 256
    int n0 = blockIdx.x * 64;              // 8 blocks
    int m0 = blockIdx.y * 16;              // 8 blocks
    int r  = tid >> 4;                     // 0..15 (row)
    int tn = (tid & 15) * 4;
    float acc[4] = {};
    for (int k0 = 0; k0 < H; k0 += 16) {
        {
            int mm = tid >> 4, kk = tid & 15;
            As[mm][kk] = g_h[(size_t)(m0 + mm) * H + k0 + kk];
        }
        #pragma unroll
        for (int i = 0; i < 4; i++) {
            int idx = tid + i * 256;
            int kk = idx >> 6, nn = idx & 63;
            Bs[kk][nn] = Wh[(size_t)(k0 + kk) * H + n0 + nn];
        }
        __syncthreads();
        #pragma unroll
        for (int k = 0; k < 16; k++) {
            float a = As[r][k];
            acc[0] += a * Bs[k][tn];
            acc[1] += a * Bs[k][tn + 1];
            acc[2] += a * Bs[k][tn + 2];
            acc[3] += a * Bs[k][tn + 3];
        }
        __syncthreads();
    }
    #pragma unroll
    for (int j = 0; j < 4; j++)
        g_hw[(size_t)(m0 + r) * H + n0 + tn + j] = acc[j];
}

// ---------------- attention: scores, softmax, attended ----------------------
__global__ void attn_kernel(const float* __restrict__ wo, const float* __restrict__ area, int t)
{
    int bb = blockIdx.x, tid = threadIdx.x;   // 128 blocks x 256
    __shared__ float shw[512];
    __shared__ float swo[512];
    __shared__ float sal[52];
    shw[tid]       = g_hw[(size_t)bb * H + tid];
    shw[tid + 256] = g_hw[(size_t)bb * H + tid + 256];
    swo[tid]       = wo[tid];
    swo[tid + 256] = wo[tid + 256];
    __syncthreads();
    int warp = tid >> 5, lane = tid & 31;
    for (int f = warp; f < F; f += 8) {
        const float* vp = g_Vproj + ((size_t)bb * F + f) * H;
        float s = 0.f;
        for (int k = lane; k < H; k += 32)
            s += swo[k] * tanhf(vp[k] + shw[k]);
        #pragma unroll
        for (int off = 16; off; off >>= 1)
            s += __shfl_xor_sync(0xffffffffu, s, off);
        if (lane == 0) sal[f] = s;
    }
    __syncthreads();
    if (tid < 32) {
        float v0 = (tid < F) ? sal[tid] : -3.4e38f;
        float v1 = (tid + 32 < F) ? sal[tid + 32] : -3.4e38f;
        float mx = fmaxf(v0, v1);
        #pragma unroll
        for (int off = 16; off; off >>= 1)
            mx = fmaxf(mx, __shfl_xor_sync(0xffffffffu, mx, off));
        float e0 = (tid < F) ? expf(v0 - mx) : 0.f;
        float e1 = (tid + 32 < F) ? expf(v1 - mx) : 0.f;
        float s = e0 + e1;
        #pragma unroll
        for (int off = 16; off; off >>= 1)
            s += __shfl_xor_sync(0xffffffffu, s, off);
        float inv = 1.f / s;
        if (tid < F) sal[tid] = e0 * inv;
        if (tid + 32 < F) sal[tid + 32] = e1 * inv;
    }
    __syncthreads();
    for (int h = tid; h < H; h += 256) {
        const float* ar = area + ((size_t)bb * H + h) * F;
        float s = 0.f;
        #pragma unroll
        for (int f = 0; f < F; f++) s += ar[f] * sal[f];
        g_X[((size_t)t * B + bb) * H2 + H + h] = s;
    }
}

// ---------------- final: out = X @ W_out + b_out : [2560,1024]@[1024,10000] -
__global__ void final_kernel(const float* __restrict__ W, const float* __restrict__ bias,
                             float* __restrict__ out)
{
    __shared__ float As[16][132];          // [k][m], padded
    __shared__ float Bs[16][68];           // [k][n], padded
    int tid = threadIdx.x;                 // 256
    int n0 = blockIdx.x * 64;              // 157 blocks
    int m0 = blockIdx.y * 128;             // 20 blocks
    int tm = (tid >> 4) * 8;
    int tn = (tid & 15) * 4;
    float acc[8][4] = {};
    for (int k0 = 0; k0 < H2; k0 += 16) {
        // A: 128x16 as float4, 2 per thread
        #pragma unroll
        for (int i = 0; i < 2; i++) {
            int idx = tid + i * 256;       // 0..511
            int row = idx >> 2;
            int kq = (idx & 3) * 4;
            float4 v = *(const float4*)(g_X + (size_t)(m0 + row) * H2 + k0 + kq);
            As[kq + 0][row] = v.x;
            As[kq + 1][row] = v.y;
            As[kq + 2][row] = v.z;
            As[kq + 3][row] = v.w;
        }
        // B: 16x64 scalar, 4 per thread (coalesced over n)
        #pragma unroll
        for (int i = 0; i < 4; i++) {
            int idx = tid + i * 256;       // 0..1023
            int kk = idx >> 6, nn = idx & 63;
            int n = n0 + nn;
            Bs[kk][nn] = (n < VV) ? W[(size_t)(k0 + kk) * VV + n] : 0.f;
        }
        __syncthreads();
        #pragma unroll
        for (int k = 0; k < 16; k++) {
            float4 a0 = *(const float4*)&As[k][tm];
            float4 a1 = *(const float4*)&As[k][tm + 4];
            float4 bv = *(const float4*)&Bs[k][tn];
            float a[8] = {a0.x, a0.y, a0.z, a0.w, a1.x, a1.y, a1.z, a1.w};
            float b[4] = {bv.x, bv.y, bv.z, bv.w};
            #pragma unroll
            for (int i = 0; i < 8; i++)
                #pragma unroll
                for (int j = 0; j < 4; j++)
                    acc[i][j] += a[i] * b[j];
        }
        __syncthreads();
    }
    #pragma unroll
    for (int i = 0; i < 8; i++) {
        int m = m0 + tm + i;               // = t*B + b
        int tt = m >> 7;
        int bb = m & 127;
        size_t orow = ((size_t)bb * T + tt) * VV;
        #pragma unroll
        for (int j = 0; j < 4; j++) {
            int n = n0 + tn + j;
            if (n < VV) out[orow + n] = acc[i][j] + bias[n];
        }
    }
}

// ---------------- launcher --------------------------------------------------
extern "C" void kernel_launch(void* const* d_in, const int* in_sizes, int n_in,
                              void* d_out, int out_size)
{
    const int*   cap  = (const int*)  d_in[0];   // [B,T] int32
    const float* gf   = (const float*)d_in[1];   // [B,H]
    const float* area = (const float*)d_in[2];   // [B,H,F]
    const float* h0   = (const float*)d_in[3];
    const float* c0   = (const float*)d_in[4];
    const float* emb  = (const float*)d_in[5];   // [V,H]
    const float* Wih  = (const float*)d_in[6];   // [2H,4H]
    const float* Whh  = (const float*)d_in[7];   // [H,4H]
    const float* bih  = (const float*)d_in[8];
    const float* bhh  = (const float*)d_in[9];
    const float* Wv   = (const float*)d_in[10];  // [H,H]
    const float* Wh   = (const float*)d_in[11];  // [H,H]
    const float* wo   = (const float*)d_in[12];  // [H]
    const float* Wout = (const float*)d_in[13];  // [2H,V]
    const float* bout = (const float*)d_in[14];  // [V]
    float* out = (float*)d_out;

    prep_kernel<<<256, 256>>>(h0, c0, bih, bhh);
    vproj_kernel<<<dim3(8, 98), 256>>>(area, Wv);
    for (int t = 0; t < T; t++) {
        gates_kernel<<<dim3(32, 4), 256>>>(cap, gf, emb, Wih, Whh, t);
        lstm_kernel<<<256, 256>>>(t);
        hw_kernel<<<dim3(8, 8), 256>>>(Wh);
        attn_kernel<<<128, 256>>>(wo, area, t);
    }
    final_kernel<<<dim3(157, 20), 256>>>(Wout, bout, out);
}

// round 4
// speedup vs baseline: 1.0366x; 1.0366x over previous
#include <cuda_runtime.h>
#include <cuda_bf16.h>
#include <cstdint>
#include <math.h>

// Problem constants
#define B 128
#define T 20
#define VV 10000
#define H 512
#define F 49
// derived
#define H2 1024   // 2H
#define H4 2048   // 4H
#define K3 1536   // 3H (emb | gf | h)
#define HF 25088  // H*F
#define NP 10112  // padded vocab (79*128)

// ---------------- scratch (device globals; no allocation allowed) ----------
__device__ float g_Vproj[B * F * H];        // [B,F,H]
__device__ float g_X[T * B * H2];           // [T,B,2H] rows t*B+b: [h | attended]
__device__ float g_gates[B * H4];
__device__ float g_h[B * H];
__device__ float g_c[B * H];
__device__ float g_hw[B * H];
__device__ float g_bias[H4];
// bf16 split buffers for tensor-core final GEMM
__device__ __nv_bfloat16 g_Whi[1024 * NP];
__device__ __nv_bfloat16 g_Wlo[1024 * NP];
__device__ __nv_bfloat16 g_Xhi[T * B * H2];
__device__ __nv_bfloat16 g_Xlo[T * B * H2];

// ---------------- prep: bias = b_ih + b_hh ; h,c <- h0,c0 -------------------
__global__ void prep_kernel(const float* __restrict__ h0, const float* __restrict__ c0,
                            const float* __restrict__ bih, const float* __restrict__ bhh)
{
    int idx = blockIdx.x * blockDim.x + threadIdx.x;   // 65536
    g_h[idx] = h0[idx];
    g_c[idx] = c0[idx];
    if (idx < H4) g_bias[idx] = bih[idx] + bhh[idx];
}

// ---------------- convert W_out to bf16 hi/lo, zero-padded to NP ------------
__global__ void convW_kernel(const float* __restrict__ W)
{
    int idx = blockIdx.x * blockDim.x + threadIdx.x;   // 1024*NP
    int k = idx / NP, n = idx - k * NP;
    float v = (n < VV) ? W[(size_t)k * VV + n] : 0.f;
    __nv_bfloat16 hi = __float2bfloat16(v);
    g_Whi[idx] = hi;
    g_Wlo[idx] = __float2bfloat16(v - __bfloat162float(hi));
}

// ---------------- convert X to bf16 hi/lo -----------------------------------
__global__ void convX_kernel()
{
    int idx = blockIdx.x * blockDim.x + threadIdx.x;   // T*B*H2 = 2621440
    float v = g_X[idx];
    __nv_bfloat16 hi = __float2bfloat16(v);
    g_Xhi[idx] = hi;
    g_Xlo[idx] = __float2bfloat16(v - __bfloat162float(hi));
}

// ---------------- Vproj = swap(area) @ Wv : [6272,512] @ [512,512] ----------
__global__ void vproj_kernel(const float* __restrict__ area, const float* __restrict__ Wv)
{
    __shared__ float As[16][66];
    __shared__ float Bs[16][66];
    int tid = threadIdx.x;                 // 256
    int n0 = blockIdx.x * 64;              // 8 blocks
    int m0 = blockIdx.y * 64;              // 98 blocks
    int tm = (tid >> 4) * 4;
    int tn = (tid & 15) * 4;
    float acc[4][4] = {};
    for (int k0 = 0; k0 < H; k0 += 16) {
        #pragma unroll
        for (int i = 0; i < 4; i++) {
            int idx = tid + i * 256;
            int kk = idx >> 6, mm = idx & 63;
            int m = m0 + mm;
            int bb = m / 49, ff = m % 49;
            As[kk][mm] = area[(size_t)bb * HF + (size_t)(k0 + kk) * 49 + ff];
        }
        #pragma unroll
        for (int i = 0; i < 4; i++) {
            int idx = tid + i * 256;
            int kk = idx >> 6, nn = idx & 63;
            Bs[kk][nn] = Wv[(size_t)(k0 + kk) * H + n0 + nn];
        }
        __syncthreads();
        #pragma unroll
        for (int k = 0; k < 16; k++) {
            float a[4], bb2[4];
            #pragma unroll
            for (int i = 0; i < 4; i++) a[i] = As[k][tm + i];
            #pragma unroll
            for (int j = 0; j < 4; j++) bb2[j] = Bs[k][tn + j];
            #pragma unroll
            for (int i = 0; i < 4; i++)
                #pragma unroll
                for (int j = 0; j < 4; j++)
                    acc[i][j] += a[i] * bb2[j];
        }
        __syncthreads();
    }
    #pragma unroll
    for (int i = 0; i < 4; i++)
        #pragma unroll
        for (int j = 0; j < 4; j++)
            g_Vproj[(size_t)(m0 + tm + i) * H + n0 + tn + j] = acc[i][j];
}

// ---------------- gates = [emb|gf|h] @ [W_ih;W_hh] + bias : [128,2048] ------
__global__ void gates_kernel(const int* __restrict__ cap, const float* __restrict__ gf,
                             const float* __restrict__ emb, const float* __restrict__ Wih,
                             const float* __restrict__ Whh, int t)
{
    __shared__ float As[16][34];
    __shared__ float Bs[16][66];
    __shared__ int stok[32];
    int tid = threadIdx.x;                 // 256
    int n0 = blockIdx.x * 64;              // 32 blocks
    int m0 = blockIdx.y * 32;              // 4 blocks
    if (tid < 32) stok[tid] = cap[(m0 + tid) * T + t];
    __syncthreads();
    int tm = (tid >> 4) * 2;
    int tn = (tid & 15) * 4;
    float acc[2][4] = {};
    for (int k0 = 0; k0 < K3; k0 += 16) {
        #pragma unroll
        for (int i = 0; i < 2; i++) {
            int idx = tid + i * 256;
            int mm = idx >> 4, kk = idx & 15;
            int m = m0 + mm, k = k0 + kk;
            float v;
            if (k < 512)        v = emb[(size_t)stok[mm] * H + k];
            else if (k < 1024)  v = gf[(size_t)m * H + (k - 512)];
            else                v = g_h[(size_t)m * H + (k - 1024)];
            As[kk][mm] = v;
        }
        #pragma unroll
        for (int i = 0; i < 4; i++) {
            int idx = tid + i * 256;
            int kk = idx >> 6, nn = idx & 63;
            int k = k0 + kk, n = n0 + nn;
            Bs[kk][nn] = (k < 1024) ? Wih[(size_t)k * H4 + n]
                                    : Whh[(size_t)(k - 1024) * H4 + n];
        }
        __syncthreads();
        #pragma unroll
        for (int k = 0; k < 16; k++) {
            float a0 = As[k][tm], a1 = As[k][tm + 1];
            float b0 = Bs[k][tn], b1 = Bs[k][tn + 1];
            float b2 = Bs[k][tn + 2], b3 = Bs[k][tn + 3];
            acc[0][0] += a0 * b0; acc[0][1] += a0 * b1;
            acc[0][2] += a0 * b2; acc[0][3] += a0 * b3;
            acc[1][0] += a1 * b0; acc[1][1] += a1 * b1;
            acc[1][2] += a1 * b2; acc[1][3] += a1 * b3;
        }
        __syncthreads();
    }
    #pragma unroll
    for (int i = 0; i < 2; i++)
        #pragma unroll
        for (int j = 0; j < 4; j++)
            g_gates[(size_t)(m0 + tm + i) * H4 + n0 + tn + j] =
                acc[i][j] + g_bias[n0 + tn + j];
}

// ---------------- LSTM elementwise; also writes h into X --------------------
__global__ void lstm_kernel(int t)
{
    int idx = blockIdx.x * blockDim.x + threadIdx.x;   // 65536
    int bb = idx >> 9, hh = idx & 511;
    const float* g = g_gates + (size_t)bb * H4;
    float gi = g[hh], gfv = g[512 + hh], gg = g[1024 + hh], go = g[1536 + hh];
    float si = 1.f / (1.f + expf(-gi));
    float sf = 1.f / (1.f + expf(-gfv));
    float so = 1.f / (1.f + expf(-go));
    float c = sf * g_c[idx] + si * tanhf(gg);
    float h = so * tanhf(c);
    g_c[idx] = c;
    g_h[idx] = h;
    g_X[((size_t)t * B + bb) * H2 + hh] = h;
}

// ---------------- hw = h @ Wh : [128,512] @ [512,512] -----------------------
__global__ void hw_kernel(const float* __restrict__ Wh)
{
    __shared__ float As[16][18];
    __shared__ float Bs[16][66];
    int tid = threadIdx.x;                 // 256
    int n0 = blockIdx.x * 64;              // 8 blocks
    int m0 = blockIdx.y * 16;              // 8 blocks
    int r  = tid >> 4;
    int tn = (tid & 15) * 4;
    float acc[4] = {};
    for (int k0 = 0; k0 < H; k0 += 16) {
        {
            int mm = tid >> 4, kk = tid & 15;
            As[mm][kk] = g_h[(size_t)(m0 + mm) * H + k0 + kk];
        }
        #pragma unroll
        for (int i = 0; i < 4; i++) {
            int idx = tid + i * 256;
            int kk = idx >> 6, nn = idx & 63;
            Bs[kk][nn] = Wh[(size_t)(k0 + kk) * H + n0 + nn];
        }
        __syncthreads();
        #pragma unroll
        for (int k = 0; k < 16; k++) {
            float a = As[r][k];
            acc[0] += a * Bs[k][tn];
            acc[1] += a * Bs[k][tn + 1];
            acc[2] += a * Bs[k][tn + 2];
            acc[3] += a * Bs[k][tn + 3];
        }
        __syncthreads();
    }
    #pragma unroll
    for (int j = 0; j < 4; j++)
        g_hw[(size_t)(m0 + r) * H + n0 + tn + j] = acc[j];
}

// ---------------- attention: scores, softmax, attended ----------------------
__global__ void attn_kernel(const float* __restrict__ wo, const float* __restrict__ area, int t)
{
    int bb = blockIdx.x, tid = threadIdx.x;   // 128 blocks x 256
    __shared__ float shw[512];
    __shared__ float swo[512];
    __shared__ float sal[52];
    shw[tid]       = g_hw[(size_t)bb * H + tid];
    shw[tid + 256] = g_hw[(size_t)bb * H + tid + 256];
    swo[tid]       = wo[tid];
    swo[tid + 256] = wo[tid + 256];
    __syncthreads();
    int warp = tid >> 5, lane = tid & 31;
    for (int f = warp; f < F; f += 8) {
        const float* vp = g_Vproj + ((size_t)bb * F + f) * H;
        float s = 0.f;
        for (int k = lane; k < H; k += 32)
            s += swo[k] * tanhf(vp[k] + shw[k]);
        #pragma unroll
        for (int off = 16; off; off >>= 1)
            s += __shfl_xor_sync(0xffffffffu, s, off);
        if (lane == 0) sal[f] = s;
    }
    __syncthreads();
    if (tid < 32) {
        float v0 = (tid < F) ? sal[tid] : -3.4e38f;
        float v1 = (tid + 32 < F) ? sal[tid + 32] : -3.4e38f;
        float mx = fmaxf(v0, v1);
        #pragma unroll
        for (int off = 16; off; off >>= 1)
            mx = fmaxf(mx, __shfl_xor_sync(0xffffffffu, mx, off));
        float e0 = (tid < F) ? expf(v0 - mx) : 0.f;
        float e1 = (tid + 32 < F) ? expf(v1 - mx) : 0.f;
        float s = e0 + e1;
        #pragma unroll
        for (int off = 16; off; off >>= 1)
            s += __shfl_xor_sync(0xffffffffu, s, off);
        float inv = 1.f / s;
        if (tid < F) sal[tid] = e0 * inv;
        if (tid + 32 < F) sal[tid + 32] = e1 * inv;
    }
    __syncthreads();
    for (int h = tid; h < H; h += 256) {
        const float* ar = area + ((size_t)bb * H + h) * F;
        float s = 0.f;
        #pragma unroll
        for (int f = 0; f < F; f++) s += ar[f] * sal[f];
        g_X[((size_t)t * B + bb) * H2 + H + h] = s;
    }
}

// ---------------- final GEMM on tensor cores (bf16x3 split) -----------------
// C[2560,10000] = X[2560,1024] @ W[1024,10000] + b, computed as K=3072:
// seg0: Xhi*Whi, seg1: Xlo*Whi, seg2: Xhi*Wlo
__device__ __forceinline__ void mma16816(float* d, unsigned a0, unsigned a1,
                                         unsigned a2, unsigned a3,
                                         unsigned b0, unsigned b1)
{
    asm volatile(
        "mma.sync.aligned.m16n8k16.row.col.f32.bf16.bf16.f32 "
        "{%0,%1,%2,%3}, {%4,%5,%6,%7}, {%8,%9}, {%0,%1,%2,%3};\n"
        : "+f"(d[0]), "+f"(d[1]), "+f"(d[2]), "+f"(d[3])
        : "r"(a0), "r"(a1), "r"(a2), "r"(a3), "r"(b0), "r"(b1));
}

__global__ __launch_bounds__(256) void final_mma_kernel(const float* __restrict__ bias,
                                                        float* __restrict__ out)
{
    __shared__ unsigned As[128][17];   // [row][c2] : 2 bf16 of row, cols 2c2,2c2+1
    __shared__ unsigned Bs[128][17];   // [n][k2]   : 2 bf16 of col n, k rows 2k2,2k2+1
    int tid = threadIdx.x;
    int lane = tid & 31, warp = tid >> 5;
    int warpM = warp >> 2, warpN = warp & 3;          // 2 x 4 warps
    int n0 = blockIdx.x * 128;                        // 79 blocks
    int m0 = blockIdx.y * 128;                        // 20 blocks
    float acc[4][4][4];
    #pragma unroll
    for (int i = 0; i < 4; i++)
        #pragma unroll
        for (int j = 0; j < 4; j++)
            #pragma unroll
            for (int q = 0; q < 4; q++) acc[i][j][q] = 0.f;

    unsigned pa[8], pb[8];
    const int NKT = 96;                               // 3072 / 32

    // precomputed per-thread load indices
    int arow[8], ac2[8], bn[8], bk2[8];
    #pragma unroll
    for (int j = 0; j < 8; j++) {
        int i = tid + j * 256;
        arow[j] = i >> 4;  ac2[j] = i & 15;
        bn[j] = i & 127;   bk2[j] = i >> 7;
    }

    // -- load tile kt into pa/pb --
    auto loadG = [&](int kt) {
        int k0 = kt * 32;
        int seg = k0 >> 10;
        int kk0 = k0 & 1023;
        const __nv_bfloat16* A = (seg == 1) ? g_Xlo : g_Xhi;
        const __nv_bfloat16* Bm = (seg == 2) ? g_Wlo : g_Whi;
        #pragma unroll
        for (int j = 0; j < 8; j++)
            pa[j] = *(const unsigned*)(A + (size_t)(m0 + arow[j]) * H2 + kk0 + ac2[j] * 2);
        #pragma unroll
        for (int j = 0; j < 8; j++) {
            const unsigned short* p = (const unsigned short*)
                (Bm + (size_t)(kk0 + 2 * bk2[j]) * NP + n0 + bn[j]);
            unsigned lo = p[0];
            unsigned hi = p[NP];
            pb[j] = lo | (hi << 16);
        }
    };
    auto storeS = [&]() {
        #pragma unroll
        for (int j = 0; j < 8; j++) As[arow[j]][ac2[j]] = pa[j];
        #pragma unroll
        for (int j = 0; j < 8; j++) Bs[bn[j]][bk2[j]] = pb[j];
    };

    loadG(0);
    storeS();
    __syncthreads();

    for (int kt = 0; kt < NKT; kt++) {
        if (kt + 1 < NKT) loadG(kt + 1);
        #pragma unroll
        for (int s = 0; s < 2; s++) {
            unsigned bf[4][2];
            #pragma unroll
            for (int nt = 0; nt < 4; nt++) {
                int n = warpN * 32 + nt * 8 + (lane >> 2);
                bf[nt][0] = Bs[n][(lane & 3) + s * 8];
                bf[nt][1] = Bs[n][(lane & 3) + 4 + s * 8];
            }
            #pragma unroll
            for (int mt = 0; mt < 4; mt++) {
                int r = warpM * 64 + mt * 16 + (lane >> 2);
                unsigned a0 = As[r][(lane & 3) + s * 8];
                unsigned a1 = As[r + 8][(lane & 3) + s * 8];
                unsigned a2 = As[r][(lane & 3) + 4 + s * 8];
                unsigned a3 = As[r + 8][(lane & 3) + 4 + s * 8];
                #pragma unroll
                for (int nt = 0; nt < 4; nt++)
                    mma16816(acc[mt][nt], a0, a1, a2, a3, bf[nt][0], bf[nt][1]);
            }
        }
        __syncthreads();
        if (kt + 1 < NKT) {
            storeS();
            __syncthreads();
        }
    }

    // epilogue: add bias, unscramble m=t*B+b -> out[b][t][vocab]
    #pragma unroll
    for (int mt = 0; mt < 4; mt++) {
        int mrow = m0 + warpM * 64 + mt * 16 + (lane >> 2);
        #pragma unroll
        for (int half = 0; half < 2; half++) {
            int m = mrow + half * 8;
            int tt = m >> 7, bb = m & 127;
            size_t orow = ((size_t)bb * T + tt) * VV;
            #pragma unroll
            for (int nt = 0; nt < 4; nt++) {
                int n = n0 + warpN * 32 + nt * 8 + (lane & 3) * 2;
                if (n < VV)     out[orow + n]     = acc[mt][nt][half * 2]     + bias[n];
                if (n + 1 < VV) out[orow + n + 1] = acc[mt][nt][half * 2 + 1] + bias[n + 1];
            }
        }
    }
}

// ---------------- launcher --------------------------------------------------
extern "C" void kernel_launch(void* const* d_in, const int* in_sizes, int n_in,
                              void* d_out, int out_size)
{
    const int*   cap  = (const int*)  d_in[0];   // [B,T] int32
    const float* gf   = (const float*)d_in[1];   // [B,H]
    const float* area = (const float*)d_in[2];   // [B,H,F]
    const float* h0   = (const float*)d_in[3];
    const float* c0   = (const float*)d_in[4];
    const float* emb  = (const float*)d_in[5];   // [V,H]
    const float* Wih  = (const float*)d_in[6];   // [2H,4H]
    const float* Whh  = (const float*)d_in[7];   // [H,4H]
    const float* bih  = (const float*)d_in[8];
    const float* bhh  = (const float*)d_in[9];
    const float* Wv   = (const float*)d_in[10];  // [H,H]
    const float* Wh   = (const float*)d_in[11];  // [H,H]
    const float* wo   = (const float*)d_in[12];  // [H]
    const float* Wout = (const float*)d_in[13];  // [2H,V]
    const float* bout = (const float*)d_in[14];  // [V]
    float* out = (float*)d_out;

    prep_kernel<<<256, 256>>>(h0, c0, bih, bhh);
    convW_kernel<<<(1024 * NP) / 256, 256>>>(Wout);
    vproj_kernel<<<dim3(8, 98), 256>>>(area, Wv);
    for (int t = 0; t < T; t++) {
        gates_kernel<<<dim3(32, 4), 256>>>(cap, gf, emb, Wih, Whh, t);
        lstm_kernel<<<256, 256>>>(t);
        hw_kernel<<<dim3(8, 8), 256>>>(Wh);
        attn_kernel<<<128, 256>>>(wo, area, t);
    }
    convX_kernel<<<(T * B * H2) / 256, 256>>>();
    final_mma_kernel<<<dim3(79, 20), 256>>>(bout, out);
}

// round 6
// speedup vs baseline: 1.5180x; 1.4644x over previous
#include <cuda_runtime.h>
#include <cuda_bf16.h>
#include <cstdint>
#include <math.h>

// Problem constants
#define B 128
#define T 20
#define VV 10000
#define H 512
#define F 49
// derived
#define H2 1024   // 2H
#define H4 2048   // 4H
#define HF 25088  // H*F
#define NP 10112  // padded vocab (79*128)
#define MM (T*B)  // 2560 rows of P / X

// ---------------- scratch (device globals; no allocation allowed) ----------
__device__ float g_Vproj[B * F * H];        // [B,F,H]
__device__ float g_X[MM * H2];              // [T,B,2H] rows t*B+b: [h | attended]
__device__ float g_hA[B * H];
__device__ float g_hB[B * H];
__device__ float g_c[B * H];
__device__ float g_hw[B * H];
__device__ float g_P[MM * H4];              // precomputed input gates (permuted cols)
__device__ float g_biasP[H4];               // permuted bias
__device__ float g_Whh_p[H * H4];           // [512, 2048] permuted Whh
// bf16 split buffers
__device__ __nv_bfloat16 g_Whi[1024 * NP];
__device__ __nv_bfloat16 g_Wlo[1024 * NP];
__device__ __nv_bfloat16 g_Xhi[MM * H2];
__device__ __nv_bfloat16 g_Xlo[MM * H2];
__device__ __nv_bfloat16 g_WihHi[1024 * H4];
__device__ __nv_bfloat16 g_WihLo[1024 * H4];
__device__ __nv_bfloat16 g_Phi[MM * H2];    // [emb|gf] rows, bf16 hi
__device__ __nv_bfloat16 g_Plo[MM * H2];

__device__ __forceinline__ float fast_tanh(float x)
{
    float e = __expf(2.f * x);
    return 1.f - __fdividef(2.f, e + 1.f);
}

// ---------------- prep: h,c <- h0,c0 ----------------------------------------
__global__ void prep_kernel(const float* __restrict__ h0, const float* __restrict__ c0)
{
    int idx = blockIdx.x * blockDim.x + threadIdx.x;   // 65536
    g_hA[idx] = h0[idx];
    g_c[idx]  = c0[idx];
}

// ---------------- convert W_out to bf16 hi/lo, zero-padded to NP ------------
__global__ void convW_kernel(const float* __restrict__ W)
{
    int idx = blockIdx.x * blockDim.x + threadIdx.x;   // 1024*NP
    int k = idx / NP, n = idx - k * NP;
    float v = (n < VV) ? W[(size_t)k * VV + n] : 0.f;
    __nv_bfloat16 hi = __float2bfloat16(v);
    g_Whi[idx] = hi;
    g_Wlo[idx] = __float2bfloat16(v - __bfloat162float(hi));
}

// ---------------- convert W_ih (permuted cols) + biasP ----------------------
// permuted col p: hh=p/4, q=p%4 -> orig col q*512+hh  (gate order i,f,g,o)
__global__ void convWih_kernel(const float* __restrict__ Wih,
                               const float* __restrict__ bih, const float* __restrict__ bhh)
{
    int idx = blockIdx.x * blockDim.x + threadIdx.x;   // 1024*2048
    int k = idx >> 11, p = idx & 2047;
    int hh = p >> 2, q = p & 3;
    int n = q * 512 + hh;
    float v = Wih[(size_t)k * H4 + n];
    __nv_bfloat16 hi = __float2bfloat16(v);
    g_WihHi[idx] = hi;
    g_WihLo[idx] = __float2bfloat16(v - __bfloat162float(hi));
    if (k == 0) g_biasP[p] = bih[n] + bhh[n];
}

// ---------------- build Whh permuted fp32 -----------------------------------
__global__ void convWhh_kernel(const float* __restrict__ Whh)
{
    int idx = blockIdx.x * blockDim.x + threadIdx.x;   // 512*2048
    int k = idx >> 11, p = idx & 2047;
    int hh = p >> 2, q = p & 3;
    g_Whh_p[idx] = Whh[(size_t)k * H4 + q * 512 + hh];
}

// ---------------- gather [emb|gf] rows -> bf16 hi/lo ------------------------
__global__ void gatherX_kernel(const int* __restrict__ cap, const float* __restrict__ gf,
                               const float* __restrict__ emb)
{
    int idx = blockIdx.x * blockDim.x + threadIdx.x;   // MM*1024
    int m = idx >> 10, k = idx & 1023;
    int bb = m & 127, tt = m >> 7;
    float v;
    if (k < 512) {
        int tok = cap[bb * T + tt];
        v = emb[(size_t)tok * H + k];
    } else {
        v = gf[(size_t)bb * H + (k - 512)];
    }
    __nv_bfloat16 hi = __float2bfloat16(v);
    g_Phi[idx] = hi;
    g_Plo[idx] = __float2bfloat16(v - __bfloat162float(hi));
}

// ---------------- Vproj = swap(area) @ Wv : [6272,512] @ [512,512] ----------
__global__ void vproj_kernel(const float* __restrict__ area, const float* __restrict__ Wv)
{
    __shared__ float As[16][66];
    __shared__ float Bs[16][66];
    int tid = threadIdx.x;                 // 256
    int n0 = blockIdx.x * 64;              // 8 blocks
    int m0 = blockIdx.y * 64;              // 98 blocks
    int tm = (tid >> 4) * 4;
    int tn = (tid & 15) * 4;
    float acc[4][4] = {};
    for (int k0 = 0; k0 < H; k0 += 16) {
        #pragma unroll
        for (int i = 0; i < 4; i++) {
            int idx = tid + i * 256;
            int kk = idx >> 6, mm = idx & 63;
            int m = m0 + mm;
            int bb = m / 49, ff = m % 49;
            As[kk][mm] = area[(size_t)bb * HF + (size_t)(k0 + kk) * 49 + ff];
        }
        #pragma unroll
        for (int i = 0; i < 4; i++) {
            int idx = tid + i * 256;
            int kk = idx >> 6, nn = idx & 63;
            Bs[kk][nn] = Wv[(size_t)(k0 + kk) * H + n0 + nn];
        }
        __syncthreads();
        #pragma unroll
        for (int k = 0; k < 16; k++) {
            float a[4], bb2[4];
            #pragma unroll
            for (int i = 0; i < 4; i++) a[i] = As[k][tm + i];
            #pragma unroll
            for (int j = 0; j < 4; j++) bb2[j] = Bs[k][tn + j];
            #pragma unroll
            for (int i = 0; i < 4; i++)
                #pragma unroll
                for (int j = 0; j < 4; j++)
                    acc[i][j] += a[i] * bb2[j];
        }
        __syncthreads();
    }
    #pragma unroll
    for (int i = 0; i < 4; i++)
        #pragma unroll
        for (int j = 0; j < 4; j++)
            g_Vproj[(size_t)(m0 + tm + i) * H + n0 + tn + j] = acc[i][j];
}

// ---------------- bf16x3 MMA helper -----------------------------------------
__device__ __forceinline__ void mma16816(float* d, unsigned a0, unsigned a1,
                                         unsigned a2, unsigned a3,
                                         unsigned b0, unsigned b1)
{
    asm volatile(
        "mma.sync.aligned.m16n8k16.row.col.f32.bf16.bf16.f32 "
        "{%0,%1,%2,%3}, {%4,%5,%6,%7}, {%8,%9}, {%0,%1,%2,%3};\n"
        : "+f"(d[0]), "+f"(d[1]), "+f"(d[2]), "+f"(d[3])
        : "r"(a0), "r"(a1), "r"(a2), "r"(a3), "r"(b0), "r"(b1));
}

// ---------------- P = [emb|gf] @ Wih_perm + biasP : [2560,1024]@[1024,2048] -
__global__ __launch_bounds__(256) void pgemm_kernel()
{
    __shared__ unsigned As[128][17];
    __shared__ unsigned Bs[128][17];
    int tid = threadIdx.x;
    int lane = tid & 31, warp = tid >> 5;
    int warpM = warp >> 2, warpN = warp & 3;
    int n0 = blockIdx.x * 128;                        // 16 blocks
    int m0 = blockIdx.y * 128;                        // 20 blocks
    float acc[4][4][4];
    #pragma unroll
    for (int i = 0; i < 4; i++)
        #pragma unroll
        for (int j = 0; j < 4; j++)
            #pragma unroll
            for (int q = 0; q < 4; q++) acc[i][j][q] = 0.f;

    unsigned pa[8], pb[8];
    const int NKT = 96;
    int arow[8], ac2[8], bn[8], bk2[8];
    #pragma unroll
    for (int j = 0; j < 8; j++) {
        int i = tid + j * 256;
        arow[j] = i >> 4;  ac2[j] = i & 15;
        bn[j] = i & 127;   bk2[j] = i >> 7;
    }
    auto loadG = [&](int kt) {
        int k0 = kt * 32;
        int seg = k0 >> 10;
        int kk0 = k0 & 1023;
        const __nv_bfloat16* A = (seg == 1) ? g_Plo : g_Phi;
        const __nv_bfloat16* Bm = (seg == 2) ? g_WihLo : g_WihHi;
        #pragma unroll
        for (int j = 0; j < 8; j++)
            pa[j] = *(const unsigned*)(A + (size_t)(m0 + arow[j]) * H2 + kk0 + ac2[j] * 2);
        #pragma unroll
        for (int j = 0; j < 8; j++) {
            const unsigned short* p = (const unsigned short*)
                (Bm + (size_t)(kk0 + 2 * bk2[j]) * H4 + n0 + bn[j]);
            unsigned lo = p[0];
            unsigned hi = p[H4];
            pb[j] = lo | (hi << 16);
        }
    };
    auto storeS = [&]() {
        #pragma unroll
        for (int j = 0; j < 8; j++) As[arow[j]][ac2[j]] = pa[j];
        #pragma unroll
        for (int j = 0; j < 8; j++) Bs[bn[j]][bk2[j]] = pb[j];
    };
    loadG(0); storeS(); __syncthreads();
    for (int kt = 0; kt < NKT; kt++) {
        if (kt + 1 < NKT) loadG(kt + 1);
        #pragma unroll
        for (int s = 0; s < 2; s++) {
            unsigned bf[4][2];
            #pragma unroll
            for (int nt = 0; nt < 4; nt++) {
                int n = warpN * 32 + nt * 8 + (lane >> 2);
                bf[nt][0] = Bs[n][(lane & 3) + s * 8];
                bf[nt][1] = Bs[n][(lane & 3) + 4 + s * 8];
            }
            #pragma unroll
            for (int mt = 0; mt < 4; mt++) {
                int r = warpM * 64 + mt * 16 + (lane >> 2);
                unsigned a0 = As[r][(lane & 3) + s * 8];
                unsigned a1 = As[r + 8][(lane & 3) + s * 8];
                unsigned a2 = As[r][(lane & 3) + 4 + s * 8];
                unsigned a3 = As[r + 8][(lane & 3) + 4 + s * 8];
                #pragma unroll
                for (int nt = 0; nt < 4; nt++)
                    mma16816(acc[mt][nt], a0, a1, a2, a3, bf[nt][0], bf[nt][1]);
            }
        }
        __syncthreads();
        if (kt + 1 < NKT) { storeS(); __syncthreads(); }
    }
    #pragma unroll
    for (int mt = 0; mt < 4; mt++) {
        int mrow = m0 + warpM * 64 + mt * 16 + (lane >> 2);
        #pragma unroll
        for (int half = 0; half < 2; half++) {
            int m = mrow + half * 8;
            #pragma unroll
            for (int nt = 0; nt < 4; nt++) {
                int n = n0 + warpN * 32 + nt * 8 + (lane & 3) * 2;
                g_P[(size_t)m * H4 + n]     = acc[mt][nt][half * 2]     + g_biasP[n];
                g_P[(size_t)m * H4 + n + 1] = acc[mt][nt][half * 2 + 1] + g_biasP[n + 1];
            }
        }
    }
}

// ---------------- per-step fused: G = h @ Whh_p ; LSTM epilogue -------------
// grid (32, 4): bx = N-tile (64 gate cols), by = M-tile (32 rows). block 256.
__global__ __launch_bounds__(256) void step_kernel(int t)
{
    __shared__ float As[16][34];           // [k][m]
    __shared__ float Bs[16][66];           // [k][n]
    const float* hs = (t & 1) ? g_hB : g_hA;
    float* hd       = (t & 1) ? g_hA : g_hB;
    int tid = threadIdx.x;
    int n0 = blockIdx.x * 64;
    int m0 = blockIdx.y * 32;
    int ty = tid >> 4, tx = tid & 15;
    int tm = ty * 2;                       // 2 rows
    int tn = tx * 4;                       // 4 cols (one gate quadruple)
    float acc[2][4] = {};
    for (int k0 = 0; k0 < H; k0 += 16) {
        #pragma unroll
        for (int i = 0; i < 2; i++) {
            int idx = tid + i * 256;       // 0..511
            int kk = idx >> 5, mm = idx & 31;
            As[kk][mm] = hs[(size_t)(m0 + mm) * H + k0 + kk];
        }
        #pragma unroll
        for (int i = 0; i < 4; i++) {
            int idx = tid + i * 256;       // 0..1023
            int kk = idx >> 6, nn = idx & 63;
            Bs[kk][nn] = g_Whh_p[(size_t)(k0 + kk) * H4 + n0 + nn];
        }
        __syncthreads();
        #pragma unroll
        for (int k = 0; k < 16; k++) {
            float a0 = As[k][tm], a1 = As[k][tm + 1];
            float b0 = Bs[k][tn], b1 = Bs[k][tn + 1];
            float b2 = Bs[k][tn + 2], b3 = Bs[k][tn + 3];
            acc[0][0] += a0 * b0; acc[0][1] += a0 * b1;
            acc[0][2] += a0 * b2; acc[0][3] += a0 * b3;
            acc[1][0] += a1 * b0; acc[1][1] += a1 * b1;
            acc[1][2] += a1 * b2; acc[1][3] += a1 * b3;
        }
        __syncthreads();
    }
    // cols tn..tn+3 are (i,f,g,o) for hidden unit hh = (n0+tn)/4
    int hh = (n0 + tn) >> 2;
    #pragma unroll
    for (int i = 0; i < 2; i++) {
        int m = m0 + tm + i;               // = batch b
        const float* Pr = g_P + (size_t)(t * B + m) * H4 + n0 + tn;
        float gi = acc[i][0] + Pr[0];
        float gf = acc[i][1] + Pr[1];
        float gg = acc[i][2] + Pr[2];
        float go = acc[i][3] + Pr[3];
        float si = 1.f / (1.f + expf(-gi));
        float sf = 1.f / (1.f + expf(-gf));
        float so = 1.f / (1.f + expf(-go));
        int idx = m * H + hh;
        float c = sf * g_c[idx] + si * tanhf(gg);
        float h = so * tanhf(c);
        g_c[idx] = c;
        hd[idx] = h;
        g_X[((size_t)t * B + m) * H2 + hh] = h;
    }
}

// ---------------- hw = h_new @ Wh : [128,512] @ [512,512] -------------------
__global__ void hw_kernel(const float* __restrict__ Wh, int t)
{
    __shared__ float As[16][18];
    __shared__ float Bs[16][66];
    const float* hsrc = (t & 1) ? g_hA : g_hB;   // NEW h written by step_kernel
    int tid = threadIdx.x;                 // 256
    int n0 = blockIdx.x * 64;              // 8 blocks
    int m0 = blockIdx.y * 16;              // 8 blocks
    int r  = tid >> 4;
    int tn = (tid & 15) * 4;
    float acc[4] = {};
    for (int k0 = 0; k0 < H; k0 += 16) {
        {
            int mm = tid >> 4, kk = tid & 15;
            As[mm][kk] = hsrc[(size_t)(m0 + mm) * H + k0 + kk];
        }
        #pragma unroll
        for (int i = 0; i < 4; i++) {
            int idx = tid + i * 256;
            int kk = idx >> 6, nn = idx & 63;
            Bs[kk][nn] = Wh[(size_t)(k0 + kk) * H + n0 + nn];
        }
        __syncthreads();
        #pragma unroll
        for (int k = 0; k < 16; k++) {
            float a = As[r][k];
            acc[0] += a * Bs[k][tn];
            acc[1] += a * Bs[k][tn + 1];
            acc[2] += a * Bs[k][tn + 2];
            acc[3] += a * Bs[k][tn + 3];
        }
        __syncthreads();
    }
    #pragma unroll
    for (int j = 0; j < 4; j++)
        g_hw[(size_t)(m0 + r) * H + n0 + tn + j] = acc[j];
}

// ---------------- attention: scores, softmax, attended ----------------------
__global__ void attn_kernel(const float* __restrict__ wo, const float* __restrict__ area, int t)
{
    int bb = blockIdx.x, tid = threadIdx.x;   // 128 blocks x 256
    __shared__ float shw[512];
    __shared__ float swo[512];
    __shared__ float sal[52];
    shw[tid]       = g_hw[(size_t)bb * H + tid];
    shw[tid + 256] = g_hw[(size_t)bb * H + tid + 256];
    swo[tid]       = wo[tid];
    swo[tid + 256] = wo[tid + 256];
    __syncthreads();
    int warp = tid >> 5, lane = tid & 31;
    for (int f = warp; f < F; f += 8) {
        const float* vp = g_Vproj + ((size_t)bb * F + f) * H;
        float s = 0.f;
        for (int k = lane; k < H; k += 32)
            s += swo[k] * fast_tanh(vp[k] + shw[k]);
        #pragma unroll
        for (int off = 16; off; off >>= 1)
            s += __shfl_xor_sync(0xffffffffu, s, off);
        if (lane == 0) sal[f] = s;
    }
    __syncthreads();
    if (tid < 32) {
        float v0 = (tid < F) ? sal[tid] : -3.4e38f;
        float v1 = (tid + 32 < F) ? sal[tid + 32] : -3.4e38f;
        float mx = fmaxf(v0, v1);
        #pragma unroll
        for (int off = 16; off; off >>= 1)
            mx = fmaxf(mx, __shfl_xor_sync(0xffffffffu, mx, off));
        float e0 = (tid < F) ? expf(v0 - mx) : 0.f;
        float e1 = (tid + 32 < F) ? expf(v1 - mx) : 0.f;
        float s = e0 + e1;
        #pragma unroll
        for (int off = 16; off; off >>= 1)
            s += __shfl_xor_sync(0xffffffffu, s, off);
        float inv = 1.f / s;
        if (tid < F) sal[tid] = e0 * inv;
        if (tid + 32 < F) sal[tid + 32] = e1 * inv;
    }
    __syncthreads();
    for (int h = tid; h < H; h += 256) {
        const float* ar = area + ((size_t)bb * H + h) * F;
        float s = 0.f;
        #pragma unroll
        for (int f = 0; f < F; f++) s += ar[f] * sal[f];
        g_X[((size_t)t * B + bb) * H2 + H + h] = s;
    }
}

// ---------------- convert X to bf16 hi/lo -----------------------------------
__global__ void convX_kernel()
{
    int idx = blockIdx.x * blockDim.x + threadIdx.x;   // MM*H2
    float v = g_X[idx];
    __nv_bfloat16 hi = __float2bfloat16(v);
    g_Xhi[idx] = hi;
    g_Xlo[idx] = __float2bfloat16(v - __bfloat162float(hi));
}

// ---------------- final: out = X @ W_out + b_out (bf16x3 MMA) ---------------
__global__ __launch_bounds__(256) void final_mma_kernel(const float* __restrict__ bias,
                                                        float* __restrict__ out)
{
    __shared__ unsigned As[128][17];
    __shared__ unsigned Bs[128][17];
    int tid = threadIdx.x;
    int lane = tid & 31, warp = tid >> 5;
    int warpM = warp >> 2, warpN = warp & 3;
    int n0 = blockIdx.x * 128;                        // 79 blocks
    int m0 = blockIdx.y * 128;                        // 20 blocks
    float acc[4][4][4];
    #pragma unroll
    for (int i = 0; i < 4; i++)
        #pragma unroll
        for (int j = 0; j < 4; j++)
            #pragma unroll
            for (int q = 0; q < 4; q++) acc[i][j][q] = 0.f;

    unsigned pa[8], pb[8];
    const int NKT = 96;
    int arow[8], ac2[8], bn[8], bk2[8];
    #pragma unroll
    for (int j = 0; j < 8; j++) {
        int i = tid + j * 256;
        arow[j] = i >> 4;  ac2[j] = i & 15;
        bn[j] = i & 127;   bk2[j] = i >> 7;
    }
    auto loadG = [&](int kt) {
        int k0 = kt * 32;
        int seg = k0 >> 10;
        int kk0 = k0 & 1023;
        const __nv_bfloat16* A = (seg == 1) ? g_Xlo : g_Xhi;
        const __nv_bfloat16* Bm = (seg == 2) ? g_Wlo : g_Whi;
        #pragma unroll
        for (int j = 0; j < 8; j++)
            pa[j] = *(const unsigned*)(A + (size_t)(m0 + arow[j]) * H2 + kk0 + ac2[j] * 2);
        #pragma unroll
        for (int j = 0; j < 8; j++) {
            const unsigned short* p = (const unsigned short*)
                (Bm + (size_t)(kk0 + 2 * bk2[j]) * NP + n0 + bn[j]);
            unsigned lo = p[0];
            unsigned hi = p[NP];
            pb[j] = lo | (hi << 16);
        }
    };
    auto storeS = [&]() {
        #pragma unroll
        for (int j = 0; j < 8; j++) As[arow[j]][ac2[j]] = pa[j];
        #pragma unroll
        for (int j = 0; j < 8; j++) Bs[bn[j]][bk2[j]] = pb[j];
    };
    loadG(0); storeS(); __syncthreads();
    for (int kt = 0; kt < NKT; kt++) {
        if (kt + 1 < NKT) loadG(kt + 1);
        #pragma unroll
        for (int s = 0; s < 2; s++) {
            unsigned bf[4][2];
            #pragma unroll
            for (int nt = 0; nt < 4; nt++) {
                int n = warpN * 32 + nt * 8 + (lane >> 2);
                bf[nt][0] = Bs[n][(lane & 3) + s * 8];
                bf[nt][1] = Bs[n][(lane & 3) + 4 + s * 8];
            }
            #pragma unroll
            for (int mt = 0; mt < 4; mt++) {
                int r = warpM * 64 + mt * 16 + (lane >> 2);
                unsigned a0 = As[r][(lane & 3) + s * 8];
                unsigned a1 = As[r + 8][(lane & 3) + s * 8];
                unsigned a2 = As[r][(lane & 3) + 4 + s * 8];
                unsigned a3 = As[r + 8][(lane & 3) + 4 + s * 8];
                #pragma unroll
                for (int nt = 0; nt < 4; nt++)
                    mma16816(acc[mt][nt], a0, a1, a2, a3, bf[nt][0], bf[nt][1]);
            }
        }
        __syncthreads();
        if (kt + 1 < NKT) { storeS(); __syncthreads(); }
    }
    #pragma unroll
    for (int mt = 0; mt < 4; mt++) {
        int mrow = m0 + warpM * 64 + mt * 16 + (lane >> 2);
        #pragma unroll
        for (int half = 0; half < 2; half++) {
            int m = mrow + half * 8;
            int tt = m >> 7, bb = m & 127;
            size_t orow = ((size_t)bb * T + tt) * VV;
            #pragma unroll
            for (int nt = 0; nt < 4; nt++) {
                int n = n0 + warpN * 32 + nt * 8 + (lane & 3) * 2;
                if (n < VV)     out[orow + n]     = acc[mt][nt][half * 2]     + bias[n];
                if (n + 1 < VV) out[orow + n + 1] = acc[mt][nt][half * 2 + 1] + bias[n + 1];
            }
        }
    }
}

// ---------------- launcher --------------------------------------------------
extern "C" void kernel_launch(void* const* d_in, const int* in_sizes, int n_in,
                              void* d_out, int out_size)
{
    const int*   cap  = (const int*)  d_in[0];   // [B,T] int32
    const float* gf   = (const float*)d_in[1];   // [B,H]
    const float* area = (const float*)d_in[2];   // [B,H,F]
    const float* h0   = (const float*)d_in[3];
    const float* c0   = (const float*)d_in[4];
    const float* emb  = (const float*)d_in[5];   // [V,H]
    const float* Wih  = (const float*)d_in[6];   // [2H,4H]
    const float* Whh  = (const float*)d_in[7];   // [H,4H]
    const float* bih  = (const float*)d_in[8];
    const float* bhh  = (const float*)d_in[9];
    const float* Wv   = (const float*)d_in[10];  // [H,H]
    const float* Wh   = (const float*)d_in[11];  // [H,H]
    const float* wo   = (const float*)d_in[12];  // [H]
    const float* Wout = (const float*)d_in[13];  // [2H,V]
    const float* bout = (const float*)d_in[14];  // [V]
    float* out = (float*)d_out;

    prep_kernel<<<256, 256>>>(h0, c0);
    convW_kernel<<<(1024 * NP) / 256, 256>>>(Wout);
    convWih_kernel<<<(1024 * H4) / 256, 256>>>(Wih, bih, bhh);
    convWhh_kernel<<<(H * H4) / 256, 256>>>(Whh);
    gatherX_kernel<<<(MM * H2) / 256, 256>>>(cap, gf, emb);
    pgemm_kernel<<<dim3(16, 20), 256>>>();
    vproj_kernel<<<dim3(8, 98), 256>>>(area, Wv);
    for (int t = 0; t < T; t++) {
        step_kernel<<<dim3(32, 4), 256>>>(t);
        hw_kernel<<<dim3(8, 8), 256>>>(Wh, t);
        attn_kernel<<<128, 256>>>(wo, area, t);
    }
    convX_kernel<<<(MM * H2) / 256, 256>>>();
    final_mma_kernel<<<dim3(79, 20), 256>>>(bout, out);
}

// round 7
// speedup vs baseline: 1.8258x; 1.2028x over previous
#include <cuda_runtime.h>
#include <cuda_fp16.h>
#include <cstdint>
#include <math.h>

// Problem constants
#define B 128
#define T 20
#define VV 10000
#define H 512
#define F 49
// derived
#define H2 1024   // 2H
#define H4 2048   // 4H
#define HF 25088  // H*F
#define NP 10112  // padded vocab (79*128)
#define MM (T*B)  // 2560 rows of P / X

// ---------------- scratch (device globals; no allocation allowed) ----------
__device__ float g_Vproj[B * F * H];        // [B,F,H]
__device__ float g_X[MM * H2];              // [T,B,2H] rows t*B+b: [h | attended]
__device__ float g_hA[B * H];
__device__ float g_hB[B * H];
__device__ float g_c[B * H];
__device__ float g_hw[B * H];
__device__ float g_P[MM * H4];              // precomputed input gates (permuted cols)
__device__ float g_biasP[H4];               // permuted bias
__device__ float g_Whh_p[H * H4];           // [512, 2048] permuted Whh
// fp16 split buffers (packed B words: (k,k+1) pair per 32-bit word)
__device__ unsigned g_WoPk[512 * NP];       // W_out hi, packed [k2][n]
__device__ unsigned g_WihPkHi[512 * H4];    // Wih permuted hi, packed [k2][p]
__device__ unsigned g_WihPkLo[512 * H4];
__device__ __half g_Xhi[MM * H2];
__device__ __half g_Xlo[MM * H2];
__device__ __half g_Phi[MM * H2];           // [emb|gf] rows
__device__ __half g_Plo[MM * H2];

__device__ __forceinline__ float fast_tanh(float x)
{
    float e = __expf(2.f * x);
    return 1.f - __fdividef(2.f, e + 1.f);
}

// ---------------- prep: h,c <- h0,c0 ----------------------------------------
__global__ void prep_kernel(const float* __restrict__ h0, const float* __restrict__ c0)
{
    int idx = blockIdx.x * blockDim.x + threadIdx.x;   // 65536
    g_hA[idx] = h0[idx];
    g_c[idx]  = c0[idx];
}

// ---------------- W_out -> fp16 hi packed words, zero-padded to NP ----------
__global__ void convW_kernel(const float* __restrict__ W)
{
    int idx = blockIdx.x * blockDim.x + threadIdx.x;   // 512*NP
    int k2 = idx / NP, n = idx - k2 * NP;
    float v0 = 0.f, v1 = 0.f;
    if (n < VV) {
        v0 = W[(size_t)(2 * k2) * VV + n];
        v1 = W[(size_t)(2 * k2 + 1) * VV + n];
    }
    unsigned lo = __half_as_ushort(__float2half_rn(v0));
    unsigned hi = __half_as_ushort(__float2half_rn(v1));
    g_WoPk[idx] = lo | (hi << 16);
}

// ---------------- W_ih permuted -> fp16 hi/lo packed + biasP ----------------
// permuted col p: hh=p/4, q=p%4 -> orig col q*512+hh  (gate order i,f,g,o)
__global__ void convWih_kernel(const float* __restrict__ Wih,
                               const float* __restrict__ bih, const float* __restrict__ bhh)
{
    int idx = blockIdx.x * blockDim.x + threadIdx.x;   // 512*2048
    int k2 = idx >> 11, p = idx & 2047;
    int hh = p >> 2, q = p & 3;
    int n = q * 512 + hh;
    float v0 = Wih[(size_t)(2 * k2) * H4 + n];
    float v1 = Wih[(size_t)(2 * k2 + 1) * H4 + n];
    __half h0 = __float2half_rn(v0);
    __half h1 = __float2half_rn(v1);
    float r0 = v0 - __half2float(h0);
    float r1 = v1 - __half2float(h1);
    g_WihPkHi[idx] = (unsigned)__half_as_ushort(h0) |
                     ((unsigned)__half_as_ushort(h1) << 16);
    g_WihPkLo[idx] = (unsigned)__half_as_ushort(__float2half_rn(r0)) |
                     ((unsigned)__half_as_ushort(__float2half_rn(r1)) << 16);
    if (k2 == 0) g_biasP[p] = bih[n] + bhh[n];
}

// ---------------- build Whh permuted fp32 -----------------------------------
__global__ void convWhh_kernel(const float* __restrict__ Whh)
{
    int idx = blockIdx.x * blockDim.x + threadIdx.x;   // 512*2048
    int k = idx >> 11, p = idx & 2047;
    int hh = p >> 2, q = p & 3;
    g_Whh_p[idx] = Whh[(size_t)k * H4 + q * 512 + hh];
}

// ---------------- gather [emb|gf] rows -> fp16 hi/lo ------------------------
__global__ void gatherX_kernel(const int* __restrict__ cap, const float* __restrict__ gf,
                               const float* __restrict__ emb)
{
    int idx = blockIdx.x * blockDim.x + threadIdx.x;   // MM*1024
    int m = idx >> 10, k = idx & 1023;
    int bb = m & 127, tt = m >> 7;
    float v;
    if (k < 512) {
        int tok = cap[bb * T + tt];
        v = emb[(size_t)tok * H + k];
    } else {
        v = gf[(size_t)bb * H + (k - 512)];
    }
    __half hi = __float2half_rn(v);
    g_Phi[idx] = hi;
    g_Plo[idx] = __float2half_rn(v - __half2float(hi));
}

// ---------------- Vproj = swap(area) @ Wv : [6272,512] @ [512,512] ----------
__global__ void vproj_kernel(const float* __restrict__ area, const float* __restrict__ Wv)
{
    __shared__ float As[16][66];
    __shared__ float Bs[16][66];
    int tid = threadIdx.x;                 // 256
    int n0 = blockIdx.x * 64;              // 8 blocks
    int m0 = blockIdx.y * 64;              // 98 blocks
    int tm = (tid >> 4) * 4;
    int tn = (tid & 15) * 4;
    float acc[4][4] = {};
    for (int k0 = 0; k0 < H; k0 += 16) {
        #pragma unroll
        for (int i = 0; i < 4; i++) {
            int idx = tid + i * 256;
            int kk = idx >> 6, mm = idx & 63;
            int m = m0 + mm;
            int bb = m / 49, ff = m % 49;
            As[kk][mm] = area[(size_t)bb * HF + (size_t)(k0 + kk) * 49 + ff];
        }
        #pragma unroll
        for (int i = 0; i < 4; i++) {
            int idx = tid + i * 256;
            int kk = idx >> 6, nn = idx & 63;
            Bs[kk][nn] = Wv[(size_t)(k0 + kk) * H + n0 + nn];
        }
        __syncthreads();
        #pragma unroll
        for (int k = 0; k < 16; k++) {
            float a[4], bb2[4];
            #pragma unroll
            for (int i = 0; i < 4; i++) a[i] = As[k][tm + i];
            #pragma unroll
            for (int j = 0; j < 4; j++) bb2[j] = Bs[k][tn + j];
            #pragma unroll
            for (int i = 0; i < 4; i++)
                #pragma unroll
                for (int j = 0; j < 4; j++)
                    acc[i][j] += a[i] * bb2[j];
        }
        __syncthreads();
    }
    #pragma unroll
    for (int i = 0; i < 4; i++)
        #pragma unroll
        for (int j = 0; j < 4; j++)
            g_Vproj[(size_t)(m0 + tm + i) * H + n0 + tn + j] = acc[i][j];
}

// ---------------- fp16 MMA helper -------------------------------------------
__device__ __forceinline__ void mma16816(float* d, unsigned a0, unsigned a1,
                                         unsigned a2, unsigned a3,
                                         unsigned b0, unsigned b1)
{
    asm volatile(
        "mma.sync.aligned.m16n8k16.row.col.f32.f16.f16.f32 "
        "{%0,%1,%2,%3}, {%4,%5,%6,%7}, {%8,%9}, {%0,%1,%2,%3};\n"
        : "+f"(d[0]), "+f"(d[1]), "+f"(d[2]), "+f"(d[3])
        : "r"(a0), "r"(a1), "r"(a2), "r"(a3), "r"(b0), "r"(b1));
}

// ---------------- P = [emb|gf] @ Wih_perm + biasP (fp16x3, B-reuse) ---------
// [2560,1024]@[1024,2048]; terms: Phi*Whi + Plo*Whi + Phi*Wlo
__global__ __launch_bounds__(256) void pgemm_kernel()
{
    __shared__ unsigned Ah[128][17];   // [row][c2]
    __shared__ unsigned Al[128][17];
    __shared__ unsigned Bh[128][17];   // [n][k2]
    __shared__ unsigned Bl[128][17];
    int tid = threadIdx.x;
    int lane = tid & 31, warp = tid >> 5;
    int warpM = warp >> 2, warpN = warp & 3;
    int n0 = blockIdx.x * 128;                        // 16 blocks
    int m0 = blockIdx.y * 128;                        // 20 blocks
    float acc[4][4][4];
    #pragma unroll
    for (int i = 0; i < 4; i++)
        #pragma unroll
        for (int j = 0; j < 4; j++)
            #pragma unroll
            for (int q = 0; q < 4; q++) acc[i][j][q] = 0.f;

    unsigned pah[8], pal[8], pbh[8], pbl[8];
    const int NKT = 32;
    int arow[8], ac2[8], bn[8], bk2[8];
    #pragma unroll
    for (int j = 0; j < 8; j++) {
        int i = tid + j * 256;
        arow[j] = i >> 4;  ac2[j] = i & 15;
        bn[j] = i & 127;   bk2[j] = i >> 7;
    }
    auto loadG = [&](int kt) {
        int kk0 = kt * 32;
        #pragma unroll
        for (int j = 0; j < 8; j++) {
            size_t ao = (size_t)(m0 + arow[j]) * H2 + kk0 + ac2[j] * 2;
            pah[j] = *(const unsigned*)(g_Phi + ao);
            pal[j] = *(const unsigned*)(g_Plo + ao);
        }
        #pragma unroll
        for (int j = 0; j < 8; j++) {
            size_t bo = (size_t)(kt * 16 + bk2[j]) * H4 + n0 + bn[j];
            pbh[j] = g_WihPkHi[bo];
            pbl[j] = g_WihPkLo[bo];
        }
    };
    auto storeS = [&]() {
        #pragma unroll
        for (int j = 0; j < 8; j++) { Ah[arow[j]][ac2[j]] = pah[j]; Al[arow[j]][ac2[j]] = pal[j]; }
        #pragma unroll
        for (int j = 0; j < 8; j++) { Bh[bn[j]][bk2[j]] = pbh[j]; Bl[bn[j]][bk2[j]] = pbl[j]; }
    };
    loadG(0); storeS(); __syncthreads();
    for (int kt = 0; kt < NKT; kt++) {
        if (kt + 1 < NKT) loadG(kt + 1);
        #pragma unroll
        for (int s = 0; s < 2; s++) {
            unsigned bfh[4][2], bfl[4][2];
            #pragma unroll
            for (int nt = 0; nt < 4; nt++) {
                int n = warpN * 32 + nt * 8 + (lane >> 2);
                bfh[nt][0] = Bh[n][(lane & 3) + s * 8];
                bfh[nt][1] = Bh[n][(lane & 3) + 4 + s * 8];
                bfl[nt][0] = Bl[n][(lane & 3) + s * 8];
                bfl[nt][1] = Bl[n][(lane & 3) + 4 + s * 8];
            }
            #pragma unroll
            for (int mt = 0; mt < 4; mt++) {
                int r = warpM * 64 + mt * 16 + (lane >> 2);
                unsigned a0 = Ah[r][(lane & 3) + s * 8];
                unsigned a1 = Ah[r + 8][(lane & 3) + s * 8];
                unsigned a2 = Ah[r][(lane & 3) + 4 + s * 8];
                unsigned a3 = Ah[r + 8][(lane & 3) + 4 + s * 8];
                #pragma unroll
                for (int nt = 0; nt < 4; nt++)
                    mma16816(acc[mt][nt], a0, a1, a2, a3, bfh[nt][0], bfh[nt][1]);
                #pragma unroll
                for (int nt = 0; nt < 4; nt++)
                    mma16816(acc[mt][nt], a0, a1, a2, a3, bfl[nt][0], bfl[nt][1]);
                unsigned l0 = Al[r][(lane & 3) + s * 8];
                unsigned l1 = Al[r + 8][(lane & 3) + s * 8];
                unsigned l2 = Al[r][(lane & 3) + 4 + s * 8];
                unsigned l3 = Al[r + 8][(lane & 3) + 4 + s * 8];
                #pragma unroll
                for (int nt = 0; nt < 4; nt++)
                    mma16816(acc[mt][nt], l0, l1, l2, l3, bfh[nt][0], bfh[nt][1]);
            }
        }
        __syncthreads();
        if (kt + 1 < NKT) { storeS(); __syncthreads(); }
    }
    #pragma unroll
    for (int mt = 0; mt < 4; mt++) {
        int mrow = m0 + warpM * 64 + mt * 16 + (lane >> 2);
        #pragma unroll
        for (int half = 0; half < 2; half++) {
            int m = mrow + half * 8;
            #pragma unroll
            for (int nt = 0; nt < 4; nt++) {
                int n = n0 + warpN * 32 + nt * 8 + (lane & 3) * 2;
                g_P[(size_t)m * H4 + n]     = acc[mt][nt][half * 2]     + g_biasP[n];
                g_P[(size_t)m * H4 + n + 1] = acc[mt][nt][half * 2 + 1] + g_biasP[n + 1];
            }
        }
    }
}

// ---------------- per-step fused: G = h @ Whh_p ; LSTM epilogue -------------
__global__ __launch_bounds__(256) void step_kernel(int t)
{
    __shared__ float As[16][34];           // [k][m]
    __shared__ float Bs[16][66];           // [k][n]
    const float* hs = (t & 1) ? g_hB : g_hA;
    float* hd       = (t & 1) ? g_hA : g_hB;
    int tid = threadIdx.x;
    int n0 = blockIdx.x * 64;
    int m0 = blockIdx.y * 32;
    int ty = tid >> 4, tx = tid & 15;
    int tm = ty * 2;
    int tn = tx * 4;
    float acc[2][4] = {};
    for (int k0 = 0; k0 < H; k0 += 16) {
        #pragma unroll
        for (int i = 0; i < 2; i++) {
            int idx = tid + i * 256;
            int kk = idx >> 5, mm = idx & 31;
            As[kk][mm] = hs[(size_t)(m0 + mm) * H + k0 + kk];
        }
        #pragma unroll
        for (int i = 0; i < 4; i++) {
            int idx = tid + i * 256;
            int kk = idx >> 6, nn = idx & 63;
            Bs[kk][nn] = g_Whh_p[(size_t)(k0 + kk) * H4 + n0 + nn];
        }
        __syncthreads();
        #pragma unroll
        for (int k = 0; k < 16; k++) {
            float a0 = As[k][tm], a1 = As[k][tm + 1];
            float b0 = Bs[k][tn], b1 = Bs[k][tn + 1];
            float b2 = Bs[k][tn + 2], b3 = Bs[k][tn + 3];
            acc[0][0] += a0 * b0; acc[0][1] += a0 * b1;
            acc[0][2] += a0 * b2; acc[0][3] += a0 * b3;
            acc[1][0] += a1 * b0; acc[1][1] += a1 * b1;
            acc[1][2] += a1 * b2; acc[1][3] += a1 * b3;
        }
        __syncthreads();
    }
    int hh = (n0 + tn) >> 2;
    #pragma unroll
    for (int i = 0; i < 2; i++) {
        int m = m0 + tm + i;
        const float* Pr = g_P + (size_t)(t * B + m) * H4 + n0 + tn;
        float gi = acc[i][0] + Pr[0];
        float gf = acc[i][1] + Pr[1];
        float gg = acc[i][2] + Pr[2];
        float go = acc[i][3] + Pr[3];
        float si = 1.f / (1.f + expf(-gi));
        float sf = 1.f / (1.f + expf(-gf));
        float so = 1.f / (1.f + expf(-go));
        int idx = m * H + hh;
        float c = sf * g_c[idx] + si * tanhf(gg);
        float h = so * tanhf(c);
        g_c[idx] = c;
        hd[idx] = h;
        g_X[((size_t)t * B + m) * H2 + hh] = h;
    }
}

// ---------------- hw = h_new @ Wh : [128,512] @ [512,512] -------------------
__global__ void hw_kernel(const float* __restrict__ Wh, int t)
{
    __shared__ float As[16][18];
    __shared__ float Bs[16][66];
    const float* hsrc = (t & 1) ? g_hA : g_hB;   // NEW h written by step_kernel
    int tid = threadIdx.x;
    int n0 = blockIdx.x * 64;
    int m0 = blockIdx.y * 16;
    int r  = tid >> 4;
    int tn = (tid & 15) * 4;
    float acc[4] = {};
    for (int k0 = 0; k0 < H; k0 += 16) {
        {
            int mm = tid >> 4, kk = tid & 15;
            As[mm][kk] = hsrc[(size_t)(m0 + mm) * H + k0 + kk];
        }
        #pragma unroll
        for (int i = 0; i < 4; i++) {
            int idx = tid + i * 256;
            int kk = idx >> 6, nn = idx & 63;
            Bs[kk][nn] = Wh[(size_t)(k0 + kk) * H + n0 + nn];
        }
        __syncthreads();
        #pragma unroll
        for (int k = 0; k < 16; k++) {
            float a = As[r][k];
            acc[0] += a * Bs[k][tn];
            acc[1] += a * Bs[k][tn + 1];
            acc[2] += a * Bs[k][tn + 2];
            acc[3] += a * Bs[k][tn + 3];
        }
        __syncthreads();
    }
    #pragma unroll
    for (int j = 0; j < 4; j++)
        g_hw[(size_t)(m0 + r) * H + n0 + tn + j] = acc[j];
}

// ---------------- attention: scores, softmax, attended ----------------------
__global__ void attn_kernel(const float* __restrict__ wo, const float* __restrict__ area, int t)
{
    int bb = blockIdx.x, tid = threadIdx.x;   // 128 blocks x 256
    __shared__ float shw[512];
    __shared__ float swo[512];
    __shared__ float sal[52];
    shw[tid]       = g_hw[(size_t)bb * H + tid];
    shw[tid + 256] = g_hw[(size_t)bb * H + tid + 256];
    swo[tid]       = wo[tid];
    swo[tid + 256] = wo[tid + 256];
    __syncthreads();
    int warp = tid >> 5, lane = tid & 31;
    for (int f = warp; f < F; f += 8) {
        const float* vp = g_Vproj + ((size_t)bb * F + f) * H;
        float s = 0.f;
        for (int k = lane; k < H; k += 32)
            s += swo[k] * fast_tanh(vp[k] + shw[k]);
        #pragma unroll
        for (int off = 16; off; off >>= 1)
            s += __shfl_xor_sync(0xffffffffu, s, off);
        if (lane == 0) sal[f] = s;
    }
    __syncthreads();
    if (tid < 32) {
        float v0 = (tid < F) ? sal[tid] : -3.4e38f;
        float v1 = (tid + 32 < F) ? sal[tid + 32] : -3.4e38f;
        float mx = fmaxf(v0, v1);
        #pragma unroll
        for (int off = 16; off; off >>= 1)
            mx = fmaxf(mx, __shfl_xor_sync(0xffffffffu, mx, off));
        float e0 = (tid < F) ? expf(v0 - mx) : 0.f;
        float e1 = (tid + 32 < F) ? expf(v1 - mx) : 0.f;
        float s = e0 + e1;
        #pragma unroll
        for (int off = 16; off; off >>= 1)
            s += __shfl_xor_sync(0xffffffffu, s, off);
        float inv = 1.f / s;
        if (tid < F) sal[tid] = e0 * inv;
        if (tid + 32 < F) sal[tid + 32] = e1 * inv;
    }
    __syncthreads();
    for (int h = tid; h < H; h += 256) {
        const float* ar = area + ((size_t)bb * H + h) * F;
        float s = 0.f;
        #pragma unroll
        for (int f = 0; f < F; f++) s += ar[f] * sal[f];
        g_X[((size_t)t * B + bb) * H2 + H + h] = s;
    }
}

// ---------------- convert X to fp16 hi/lo -----------------------------------
__global__ void convX_kernel()
{
    int idx = blockIdx.x * blockDim.x + threadIdx.x;   // MM*H2
    float v = g_X[idx];
    __half hi = __float2half_rn(v);
    g_Xhi[idx] = hi;
    g_Xlo[idx] = __float2half_rn(v - __half2float(hi));
}

// ---------------- final: out = X @ W_out + b_out (fp16x2, B-reuse) ----------
// terms: Xhi*Whi + Xlo*Whi  (W residual dropped; err ~1.4e-4)
__global__ __launch_bounds__(256) void final_mma_kernel(const float* __restrict__ bias,
                                                        float* __restrict__ out)
{
    __shared__ unsigned Ah[128][17];
    __shared__ unsigned Al[128][17];
    __shared__ unsigned Bs[128][17];
    int tid = threadIdx.x;
    int lane = tid & 31, warp = tid >> 5;
    int warpM = warp >> 2, warpN = warp & 3;
    int n0 = blockIdx.x * 128;                        // 79 blocks
    int m0 = blockIdx.y * 128;                        // 20 blocks
    float acc[4][4][4];
    #pragma unroll
    for (int i = 0; i < 4; i++)
        #pragma unroll
        for (int j = 0; j < 4; j++)
            #pragma unroll
            for (int q = 0; q < 4; q++) acc[i][j][q] = 0.f;

    unsigned pah[8], pal[8], pb[8];
    const int NKT = 32;
    int arow[8], ac2[8], bn[8], bk2[8];
    #pragma unroll
    for (int j = 0; j < 8; j++) {
        int i = tid + j * 256;
        arow[j] = i >> 4;  ac2[j] = i & 15;
        bn[j] = i & 127;   bk2[j] = i >> 7;
    }
    auto loadG = [&](int kt) {
        int kk0 = kt * 32;
        #pragma unroll
        for (int j = 0; j < 8; j++) {
            size_t ao = (size_t)(m0 + arow[j]) * H2 + kk0 + ac2[j] * 2;
            pah[j] = *(const unsigned*)(g_Xhi + ao);
            pal[j] = *(const unsigned*)(g_Xlo + ao);
        }
        #pragma unroll
        for (int j = 0; j < 8; j++)
            pb[j] = g_WoPk[(size_t)(kt * 16 + bk2[j]) * NP + n0 + bn[j]];
    };
    auto storeS = [&]() {
        #pragma unroll
        for (int j = 0; j < 8; j++) { Ah[arow[j]][ac2[j]] = pah[j]; Al[arow[j]][ac2[j]] = pal[j]; }
        #pragma unroll
        for (int j = 0; j < 8; j++) Bs[bn[j]][bk2[j]] = pb[j];
    };
    loadG(0); storeS(); __syncthreads();
    for (int kt = 0; kt < NKT; kt++) {
        if (kt + 1 < NKT) loadG(kt + 1);
        #pragma unroll
        for (int s = 0; s < 2; s++) {
            unsigned bf[4][2];
            #pragma unroll
            for (int nt = 0; nt < 4; nt++) {
                int n = warpN * 32 + nt * 8 + (lane >> 2);
                bf[nt][0] = Bs[n][(lane & 3) + s * 8];
                bf[nt][1] = Bs[n][(lane & 3) + 4 + s * 8];
            }
            #pragma unroll
            for (int mt = 0; mt < 4; mt++) {
                int r = warpM * 64 + mt * 16 + (lane >> 2);
                unsigned a0 = Ah[r][(lane & 3) + s * 8];
                unsigned a1 = Ah[r + 8][(lane & 3) + s * 8];
                unsigned a2 = Ah[r][(lane & 3) + 4 + s * 8];
                unsigned a3 = Ah[r + 8][(lane & 3) + 4 + s * 8];
                #pragma unroll
                for (int nt = 0; nt < 4; nt++)
                    mma16816(acc[mt][nt], a0, a1, a2, a3, bf[nt][0], bf[nt][1]);
                unsigned l0 = Al[r][(lane & 3) + s * 8];
                unsigned l1 = Al[r + 8][(lane & 3) + s * 8];
                unsigned l2 = Al[r][(lane & 3) + 4 + s * 8];
                unsigned l3 = Al[r + 8][(lane & 3) + 4 + s * 8];
                #pragma unroll
                for (int nt = 0; nt < 4; nt++)
                    mma16816(acc[mt][nt], l0, l1, l2, l3, bf[nt][0], bf[nt][1]);
            }
        }
        __syncthreads();
        if (kt + 1 < NKT) { storeS(); __syncthreads(); }
    }
    #pragma unroll
    for (int mt = 0; mt < 4; mt++) {
        int mrow = m0 + warpM * 64 + mt * 16 + (lane >> 2);
        #pragma unroll
        for (int half = 0; half < 2; half++) {
            int m = mrow + half * 8;
            int tt = m >> 7, bb = m & 127;
            size_t orow = ((size_t)bb * T + tt) * VV;
            #pragma unroll
            for (int nt = 0; nt < 4; nt++) {
                int n = n0 + warpN * 32 + nt * 8 + (lane & 3) * 2;
                if (n < VV)     out[orow + n]     = acc[mt][nt][half * 2]     + bias[n];
                if (n + 1 < VV) out[orow + n + 1] = acc[mt][nt][half * 2 + 1] + bias[n + 1];
            }
        }
    }
}

// ---------------- launcher --------------------------------------------------
extern "C" void kernel_launch(void* const* d_in, const int* in_sizes, int n_in,
                              void* d_out, int out_size)
{
    const int*   cap  = (const int*)  d_in[0];   // [B,T] int32
    const float* gf   = (const float*)d_in[1];   // [B,H]
    const float* area = (const float*)d_in[2];   // [B,H,F]
    const float* h0   = (const float*)d_in[3];
    const float* c0   = (const float*)d_in[4];
    const float* emb  = (const float*)d_in[5];   // [V,H]
    const float* Wih  = (const float*)d_in[6];   // [2H,4H]
    const float* Whh  = (const float*)d_in[7];   // [H,4H]
    const float* bih  = (const float*)d_in[8];
    const float* bhh  = (const float*)d_in[9];
    const float* Wv   = (const float*)d_in[10];  // [H,H]
    const float* Wh   = (const float*)d_in[11];  // [H,H]
    const float* wo   = (const float*)d_in[12];  // [H]
    const float* Wout = (const float*)d_in[13];  // [2H,V]
    const float* bout = (const float*)d_in[14];  // [V]
    float* out = (float*)d_out;

    prep_kernel<<<256, 256>>>(h0, c0);
    convW_kernel<<<(512 * NP) / 256, 256>>>(Wout);
    convWih_kernel<<<(512 * H4) / 256, 256>>>(Wih, bih, bhh);
    convWhh_kernel<<<(H * H4) / 256, 256>>>(Whh);
    gatherX_kernel<<<(MM * H2) / 256, 256>>>(cap, gf, emb);
    pgemm_kernel<<<dim3(16, 20), 256>>>();
    vproj_kernel<<<dim3(8, 98), 256>>>(area, Wv);
    for (int t = 0; t < T; t++) {
        step_kernel<<<dim3(32, 4), 256>>>(t);
        hw_kernel<<<dim3(8, 8), 256>>>(Wh, t);
        attn_kernel<<<128, 256>>>(wo, area, t);
    }
    convX_kernel<<<(MM * H2) / 256, 256>>>();
    final_mma_kernel<<<dim3(79, 20), 256>>>(bout, out);
}

// round 8
// speedup vs baseline: 1.8269x; 1.0006x over previous
#include <cuda_runtime.h>
#include <cuda_fp16.h>
#include <cstdint>
#include <math.h>

// Problem constants
#define B 128
#define T 20
#define VV 10000
#define H 512
#define F 49
// derived
#define H2 1024   // 2H
#define H4 2048   // 4H
#define HF 25088  // H*F
#define NP 10112  // padded vocab (79*128)
#define MM (T*B)  // 2560 rows of P / X

// ---------------- scratch (device globals; no allocation allowed) ----------
__device__ float g_Vproj[B * F * H];        // [B,F,H]
__device__ float g_hA[B * H];
__device__ float g_hB[B * H];
__device__ float g_c[B * H];
__device__ float g_hw[B * H];
__device__ float g_P[MM * H4];              // precomputed input gates (permuted cols)
__device__ float g_biasP[H4];               // permuted bias
__device__ float g_Whh_p[H * H4];           // [512, 2048] permuted Whh
// fp16 split buffers (packed B words: (k,k+1) pair per 32-bit word)
__device__ unsigned g_WoPk[512 * NP];       // W_out hi, packed [k2][n]
__device__ unsigned g_WihPkHi[512 * H4];    // Wih permuted hi, packed [k2][p]
__device__ unsigned g_WihPkLo[512 * H4];
__device__ __half g_Xhi[MM * H2];
__device__ __half g_Xlo[MM * H2];
__device__ __half g_Phi[MM * H2];           // [emb|gf] rows
__device__ __half g_Plo[MM * H2];
// global barrier state
__device__ unsigned g_cnt;
__device__ volatile unsigned g_sense;

__device__ __forceinline__ float fast_tanh(float x)
{
    float e = __expf(2.f * x);
    return 1.f - __fdividef(2.f, e + 1.f);
}
__device__ __forceinline__ float fast_sig(float x)
{
    return __fdividef(1.f, 1.f + __expf(-x));
}

// sense-reversing grid barrier (all blocks must be co-resident)
__device__ __forceinline__ void gridbar(unsigned& sense)
{
    __threadfence();
    __syncthreads();
    if (threadIdx.x == 0) {
        unsigned s = sense ^ 1u;
        sense = s;
        unsigned a = atomicAdd(&g_cnt, 1u);
        if (a == gridDim.x - 1) {
            g_cnt = 0;
            __threadfence();
            g_sense = s;
        } else {
            while (g_sense != s) { __nanosleep(32); }
        }
    }
    __syncthreads();
}

// ---------------- prep: h,c <- h0,c0 ; barrier reset ------------------------
__global__ void prep_kernel(const float* __restrict__ h0, const float* __restrict__ c0)
{
    int idx = blockIdx.x * blockDim.x + threadIdx.x;   // 65536
    g_hA[idx] = h0[idx];
    g_c[idx]  = c0[idx];
    if (idx == 0) { g_cnt = 0; g_sense = 0; }
}

// ---------------- W_out -> fp16 hi packed words, zero-padded to NP ----------
__global__ void convW_kernel(const float* __restrict__ W)
{
    int idx = blockIdx.x * blockDim.x + threadIdx.x;   // 512*NP
    int k2 = idx / NP, n = idx - k2 * NP;
    float v0 = 0.f, v1 = 0.f;
    if (n < VV) {
        v0 = W[(size_t)(2 * k2) * VV + n];
        v1 = W[(size_t)(2 * k2 + 1) * VV + n];
    }
    unsigned lo = __half_as_ushort(__float2half_rn(v0));
    unsigned hi = __half_as_ushort(__float2half_rn(v1));
    g_WoPk[idx] = lo | (hi << 16);
}

// ---------------- W_ih permuted -> fp16 hi/lo packed + biasP ----------------
// permuted col p: hh=p/4, q=p%4 -> orig col q*512+hh  (gate order i,f,g,o)
__global__ void convWih_kernel(const float* __restrict__ Wih,
                               const float* __restrict__ bih, const float* __restrict__ bhh)
{
    int idx = blockIdx.x * blockDim.x + threadIdx.x;   // 512*2048
    int k2 = idx >> 11, p = idx & 2047;
    int hh = p >> 2, q = p & 3;
    int n = q * 512 + hh;
    float v0 = Wih[(size_t)(2 * k2) * H4 + n];
    float v1 = Wih[(size_t)(2 * k2 + 1) * H4 + n];
    __half h0 = __float2half_rn(v0);
    __half h1 = __float2half_rn(v1);
    float r0 = v0 - __half2float(h0);
    float r1 = v1 - __half2float(h1);
    g_WihPkHi[idx] = (unsigned)__half_as_ushort(h0) |
                     ((unsigned)__half_as_ushort(h1) << 16);
    g_WihPkLo[idx] = (unsigned)__half_as_ushort(__float2half_rn(r0)) |
                     ((unsigned)__half_as_ushort(__float2half_rn(r1)) << 16);
    if (k2 == 0) g_biasP[p] = bih[n] + bhh[n];
}

// ---------------- build Whh permuted fp32 -----------------------------------
__global__ void convWhh_kernel(const float* __restrict__ Whh)
{
    int idx = blockIdx.x * blockDim.x + threadIdx.x;   // 512*2048
    int k = idx >> 11, p = idx & 2047;
    int hh = p >> 2, q = p & 3;
    g_Whh_p[idx] = Whh[(size_t)k * H4 + q * 512 + hh];
}

// ---------------- gather [emb|gf] rows -> fp16 hi/lo ------------------------
__global__ void gatherX_kernel(const int* __restrict__ cap, const float* __restrict__ gf,
                               const float* __restrict__ emb)
{
    int idx = blockIdx.x * blockDim.x + threadIdx.x;   // MM*1024
    int m = idx >> 10, k = idx & 1023;
    int bb = m & 127, tt = m >> 7;
    float v;
    if (k < 512) {
        int tok = cap[bb * T + tt];
        v = emb[(size_t)tok * H + k];
    } else {
        v = gf[(size_t)bb * H + (k - 512)];
    }
    __half hi = __float2half_rn(v);
    g_Phi[idx] = hi;
    g_Plo[idx] = __float2half_rn(v - __half2float(hi));
}

// ---------------- Vproj = swap(area) @ Wv : [6272,512] @ [512,512] ----------
__global__ void vproj_kernel(const float* __restrict__ area, const float* __restrict__ Wv)
{
    __shared__ float As[16][66];
    __shared__ float Bs[16][66];
    int tid = threadIdx.x;                 // 256
    int n0 = blockIdx.x * 64;              // 8 blocks
    int m0 = blockIdx.y * 64;              // 98 blocks
    int tm = (tid >> 4) * 4;
    int tn = (tid & 15) * 4;
    float acc[4][4] = {};
    for (int k0 = 0; k0 < H; k0 += 16) {
        #pragma unroll
        for (int i = 0; i < 4; i++) {
            int idx = tid + i * 256;
            int kk = idx >> 6, mm = idx & 63;
            int m = m0 + mm;
            int bb = m / 49, ff = m % 49;
            As[kk][mm] = area[(size_t)bb * HF + (size_t)(k0 + kk) * 49 + ff];
        }
        #pragma unroll
        for (int i = 0; i < 4; i++) {
            int idx = tid + i * 256;
            int kk = idx >> 6, nn = idx & 63;
            Bs[kk][nn] = Wv[(size_t)(k0 + kk) * H + n0 + nn];
        }
        __syncthreads();
        #pragma unroll
        for (int k = 0; k < 16; k++) {
            float a[4], bb2[4];
            #pragma unroll
            for (int i = 0; i < 4; i++) a[i] = As[k][tm + i];
            #pragma unroll
            for (int j = 0; j < 4; j++) bb2[j] = Bs[k][tn + j];
            #pragma unroll
            for (int i = 0; i < 4; i++)
                #pragma unroll
                for (int j = 0; j < 4; j++)
                    acc[i][j] += a[i] * bb2[j];
        }
        __syncthreads();
    }
    #pragma unroll
    for (int i = 0; i < 4; i++)
        #pragma unroll
        for (int j = 0; j < 4; j++)
            g_Vproj[(size_t)(m0 + tm + i) * H + n0 + tn + j] = acc[i][j];
}

// ---------------- fp16 MMA helper -------------------------------------------
__device__ __forceinline__ void mma16816(float* d, unsigned a0, unsigned a1,
                                         unsigned a2, unsigned a3,
                                         unsigned b0, unsigned b1)
{
    asm volatile(
        "mma.sync.aligned.m16n8k16.row.col.f32.f16.f16.f32 "
        "{%0,%1,%2,%3}, {%4,%5,%6,%7}, {%8,%9}, {%0,%1,%2,%3};\n"
        : "+f"(d[0]), "+f"(d[1]), "+f"(d[2]), "+f"(d[3])
        : "r"(a0), "r"(a1), "r"(a2), "r"(a3), "r"(b0), "r"(b1));
}

// ---------------- P = [emb|gf] @ Wih_perm + biasP (fp16x3, B-reuse) ---------
__global__ __launch_bounds__(256) void pgemm_kernel()
{
    __shared__ unsigned Ah[128][17];   // [row][c2]
    __shared__ unsigned Al[128][17];
    __shared__ unsigned Bh[128][17];   // [n][k2]
    __shared__ unsigned Bl[128][17];
    int tid = threadIdx.x;
    int lane = tid & 31, warp = tid >> 5;
    int warpM = warp >> 2, warpN = warp & 3;
    int n0 = blockIdx.x * 128;                        // 16 blocks
    int m0 = blockIdx.y * 128;                        // 20 blocks
    float acc[4][4][4];
    #pragma unroll
    for (int i = 0; i < 4; i++)
        #pragma unroll
        for (int j = 0; j < 4; j++)
            #pragma unroll
            for (int q = 0; q < 4; q++) acc[i][j][q] = 0.f;

    unsigned pah[8], pal[8], pbh[8], pbl[8];
    const int NKT = 32;
    int arow[8], ac2[8], bn[8], bk2[8];
    #pragma unroll
    for (int j = 0; j < 8; j++) {
        int i = tid + j * 256;
        arow[j] = i >> 4;  ac2[j] = i & 15;
        bn[j] = i & 127;   bk2[j] = i >> 7;
    }
    auto loadG = [&](int kt) {
        int kk0 = kt * 32;
        #pragma unroll
        for (int j = 0; j < 8; j++) {
            size_t ao = (size_t)(m0 + arow[j]) * H2 + kk0 + ac2[j] * 2;
            pah[j] = *(const unsigned*)(g_Phi + ao);
            pal[j] = *(const unsigned*)(g_Plo + ao);
        }
        #pragma unroll
        for (int j = 0; j < 8; j++) {
            size_t bo = (size_t)(kt * 16 + bk2[j]) * H4 + n0 + bn[j];
            pbh[j] = g_WihPkHi[bo];
            pbl[j] = g_WihPkLo[bo];
        }
    };
    auto storeS = [&]() {
        #pragma unroll
        for (int j = 0; j < 8; j++) { Ah[arow[j]][ac2[j]] = pah[j]; Al[arow[j]][ac2[j]] = pal[j]; }
        #pragma unroll
        for (int j = 0; j < 8; j++) { Bh[bn[j]][bk2[j]] = pbh[j]; Bl[bn[j]][bk2[j]] = pbl[j]; }
    };
    loadG(0); storeS(); __syncthreads();
    for (int kt = 0; kt < NKT; kt++) {
        if (kt + 1 < NKT) loadG(kt + 1);
        #pragma unroll
        for (int s = 0; s < 2; s++) {
            unsigned bfh[4][2], bfl[4][2];
            #pragma unroll
            for (int nt = 0; nt < 4; nt++) {
                int n = warpN * 32 + nt * 8 + (lane >> 2);
                bfh[nt][0] = Bh[n][(lane & 3) + s * 8];
                bfh[nt][1] = Bh[n][(lane & 3) + 4 + s * 8];
                bfl[nt][0] = Bl[n][(lane & 3) + s * 8];
                bfl[nt][1] = Bl[n][(lane & 3) + 4 + s * 8];
            }
            #pragma unroll
            for (int mt = 0; mt < 4; mt++) {
                int r = warpM * 64 + mt * 16 + (lane >> 2);
                unsigned a0 = Ah[r][(lane & 3) + s * 8];
                unsigned a1 = Ah[r + 8][(lane & 3) + s * 8];
                unsigned a2 = Ah[r][(lane & 3) + 4 + s * 8];
                unsigned a3 = Ah[r + 8][(lane & 3) + 4 + s * 8];
                #pragma unroll
                for (int nt = 0; nt < 4; nt++)
                    mma16816(acc[mt][nt], a0, a1, a2, a3, bfh[nt][0], bfh[nt][1]);
                #pragma unroll
                for (int nt = 0; nt < 4; nt++)
                    mma16816(acc[mt][nt], a0, a1, a2, a3, bfl[nt][0], bfl[nt][1]);
                unsigned l0 = Al[r][(lane & 3) + s * 8];
                unsigned l1 = Al[r + 8][(lane & 3) + s * 8];
                unsigned l2 = Al[r][(lane & 3) + 4 + s * 8];
                unsigned l3 = Al[r + 8][(lane & 3) + 4 + s * 8];
                #pragma unroll
                for (int nt = 0; nt < 4; nt++)
                    mma16816(acc[mt][nt], l0, l1, l2, l3, bfh[nt][0], bfh[nt][1]);
            }
        }
        __syncthreads();
        if (kt + 1 < NKT) { storeS(); __syncthreads(); }
    }
    #pragma unroll
    for (int mt = 0; mt < 4; mt++) {
        int mrow = m0 + warpM * 64 + mt * 16 + (lane >> 2);
        #pragma unroll
        for (int half = 0; half < 2; half++) {
            int m = mrow + half * 8;
            #pragma unroll
            for (int nt = 0; nt < 4; nt++) {
                int n = n0 + warpN * 32 + nt * 8 + (lane & 3) * 2;
                g_P[(size_t)m * H4 + n]     = acc[mt][nt][half * 2]     + g_biasP[n];
                g_P[(size_t)m * H4 + n + 1] = acc[mt][nt][half * 2 + 1] + g_biasP[n + 1];
            }
        }
    }
}

// ---------------- persistent fused recurrence: 20 steps, 1 launch -----------
// grid 128 x 256. Per step: A gates+LSTM, bar, B hw, bar, C attention.
__global__ __launch_bounds__(256) void loop_kernel(const float* __restrict__ Wh,
                                                   const float* __restrict__ wo,
                                                   const float* __restrict__ area)
{
    __shared__ float As[16][34];           // phase A: [k][m]
    __shared__ float Bs[16][66];           // phases A/B: [k][n]
    __shared__ float Ah2[16][18];          // phase B: [m][k]
    __shared__ float shw[512];
    __shared__ float swo[512];
    __shared__ float sal[52];
    unsigned sense = 0;
    int bid = blockIdx.x;                  // 0..127
    int tid = threadIdx.x;                 // 0..255

    // invariant: wo -> smem
    swo[tid]       = wo[tid];
    swo[tid + 256] = wo[tid + 256];

    // phase A tile coords
    int an0 = (bid & 31) * 64;
    int am0 = (bid >> 5) * 32;
    int ty = tid >> 4, tx = tid & 15;
    int atm = ty * 2, atn = tx * 4;
    int hh_a = (an0 + atn) >> 2;
    // phase B tile coords (blocks 0..63)
    int bn0 = (bid & 7) * 64;
    int bm0 = (bid >> 3) * 16;
    int br  = tid >> 4;
    int btn = (tid & 15) * 4;
    int warp = tid >> 5, lane = tid & 31;

    for (int t = 0; t < T; t++) {
        const float* hs = (t & 1) ? g_hB : g_hA;
        float* hd       = (t & 1) ? g_hA : g_hB;
        // ---------------- Phase A: gates = h @ Whh_p ; LSTM -----------------
        {
            float acc[2][4] = {};
            for (int k0 = 0; k0 < H; k0 += 16) {
                #pragma unroll
                for (int i = 0; i < 2; i++) {
                    int idx = tid + i * 256;
                    int kk = idx >> 5, mm = idx & 31;
                    As[kk][mm] = hs[(size_t)(am0 + mm) * H + k0 + kk];
                }
                #pragma unroll
                for (int i = 0; i < 4; i++) {
                    int idx = tid + i * 256;
                    int kk = idx >> 6, nn = idx & 63;
                    Bs[kk][nn] = g_Whh_p[(size_t)(k0 + kk) * H4 + an0 + nn];
                }
                __syncthreads();
                #pragma unroll
                for (int k = 0; k < 16; k++) {
                    float a0 = As[k][atm], a1 = As[k][atm + 1];
                    float b0 = Bs[k][atn], b1 = Bs[k][atn + 1];
                    float b2 = Bs[k][atn + 2], b3 = Bs[k][atn + 3];
                    acc[0][0] += a0 * b0; acc[0][1] += a0 * b1;
                    acc[0][2] += a0 * b2; acc[0][3] += a0 * b3;
                    acc[1][0] += a1 * b0; acc[1][1] += a1 * b1;
                    acc[1][2] += a1 * b2; acc[1][3] += a1 * b3;
                }
                __syncthreads();
            }
            #pragma unroll
            for (int i = 0; i < 2; i++) {
                int m = am0 + atm + i;
                const float* Pr = g_P + (size_t)(t * B + m) * H4 + an0 + atn;
                float gi = acc[i][0] + Pr[0];
                float gf = acc[i][1] + Pr[1];
                float gg = acc[i][2] + Pr[2];
                float go = acc[i][3] + Pr[3];
                float si = fast_sig(gi);
                float sf = fast_sig(gf);
                float so = fast_sig(go);
                int idx = m * H + hh_a;
                float c = sf * g_c[idx] + si * fast_tanh(gg);
                float h = so * fast_tanh(c);
                g_c[idx] = c;
                hd[idx] = h;
                int xi = (t * B + m) * H2 + hh_a;
                __half hhi = __float2half_rn(h);
                g_Xhi[xi] = hhi;
                g_Xlo[xi] = __float2half_rn(h - __half2float(hhi));
            }
        }
        gridbar(sense);
        // ---------------- Phase B: hw = h_new @ Wh (blocks 0..63) -----------
        if (bid < 64) {
            float acc[4] = {};
            for (int k0 = 0; k0 < H; k0 += 16) {
                {
                    int mm = tid >> 4, kk = tid & 15;
                    Ah2[mm][kk] = hd[(size_t)(bm0 + mm) * H + k0 + kk];
                }
                #pragma unroll
                for (int i = 0; i < 4; i++) {
                    int idx = tid + i * 256;
                    int kk = idx >> 6, nn = idx & 63;
                    Bs[kk][nn] = Wh[(size_t)(k0 + kk) * H + bn0 + nn];
                }
                __syncthreads();
                #pragma unroll
                for (int k = 0; k < 16; k++) {
                    float a = Ah2[br][k];
                    acc[0] += a * Bs[k][btn];
                    acc[1] += a * Bs[k][btn + 1];
                    acc[2] += a * Bs[k][btn + 2];
                    acc[3] += a * Bs[k][btn + 3];
                }
                __syncthreads();
            }
            #pragma unroll
            for (int j = 0; j < 4; j++)
                g_hw[(size_t)(bm0 + br) * H + bn0 + btn + j] = acc[j];
        }
        gridbar(sense);
        // ---------------- Phase C: attention (block = batch row) ------------
        {
            int bb = bid;
            shw[tid]       = g_hw[(size_t)bb * H + tid];
            shw[tid + 256] = g_hw[(size_t)bb * H + tid + 256];
            __syncthreads();
            for (int f = warp; f < F; f += 8) {
                const float* vp = g_Vproj + ((size_t)bb * F + f) * H;
                float s = 0.f;
                for (int k = lane; k < H; k += 32)
                    s += swo[k] * fast_tanh(vp[k] + shw[k]);
                #pragma unroll
                for (int off = 16; off; off >>= 1)
                    s += __shfl_xor_sync(0xffffffffu, s, off);
                if (lane == 0) sal[f] = s;
            }
            __syncthreads();
            if (tid < 32) {
                float v0 = (tid < F) ? sal[tid] : -3.4e38f;
                float v1 = (tid + 32 < F) ? sal[tid + 32] : -3.4e38f;
                float mx = fmaxf(v0, v1);
                #pragma unroll
                for (int off = 16; off; off >>= 1)
                    mx = fmaxf(mx, __shfl_xor_sync(0xffffffffu, mx, off));
                float e0 = (tid < F) ? __expf(v0 - mx) : 0.f;
                float e1 = (tid + 32 < F) ? __expf(v1 - mx) : 0.f;
                float s = e0 + e1;
                #pragma unroll
                for (int off = 16; off; off >>= 1)
                    s += __shfl_xor_sync(0xffffffffu, s, off);
                float inv = __fdividef(1.f, s);
                if (tid < F) sal[tid] = e0 * inv;
                if (tid + 32 < F) sal[tid + 32] = e1 * inv;
            }
            __syncthreads();
            for (int h = tid; h < H; h += 256) {
                const float* ar = area + ((size_t)bb * H + h) * F;
                float s = 0.f;
                #pragma unroll
                for (int f = 0; f < F; f++) s += ar[f] * sal[f];
                int xi = (t * B + bb) * H2 + H + h;
                __half shi = __float2half_rn(s);
                g_Xhi[xi] = shi;
                g_Xlo[xi] = __float2half_rn(s - __half2float(shi));
            }
            __syncthreads();
        }
        // no barrier needed before next A (disjoint data; B(t+1) fenced by bar after A)
    }
}

// ---------------- final: out = X @ W_out + b_out (fp16x2, B-reuse) ----------
__global__ __launch_bounds__(256) void final_mma_kernel(const float* __restrict__ bias,
                                                        float* __restrict__ out)
{
    __shared__ unsigned Ah[128][17];
    __shared__ unsigned Al[128][17];
    __shared__ unsigned Bs[128][17];
    int tid = threadIdx.x;
    int lane = tid & 31, warp = tid >> 5;
    int warpM = warp >> 2, warpN = warp & 3;
    int n0 = blockIdx.x * 128;                        // 79 blocks
    int m0 = blockIdx.y * 128;                        // 20 blocks
    float acc[4][4][4];
    #pragma unroll
    for (int i = 0; i < 4; i++)
        #pragma unroll
        for (int j = 0; j < 4; j++)
            #pragma unroll
            for (int q = 0; q < 4; q++) acc[i][j][q] = 0.f;

    unsigned pah[8], pal[8], pb[8];
    const int NKT = 32;
    int arow[8], ac2[8], bn[8], bk2[8];
    #pragma unroll
    for (int j = 0; j < 8; j++) {
        int i = tid + j * 256;
        arow[j] = i >> 4;  ac2[j] = i & 15;
        bn[j] = i & 127;   bk2[j] = i >> 7;
    }
    auto loadG = [&](int kt) {
        int kk0 = kt * 32;
        #pragma unroll
        for (int j = 0; j < 8; j++) {
            size_t ao = (size_t)(m0 + arow[j]) * H2 + kk0 + ac2[j] * 2;
            pah[j] = *(const unsigned*)(g_Xhi + ao);
            pal[j] = *(const unsigned*)(g_Xlo + ao);
        }
        #pragma unroll
        for (int j = 0; j < 8; j++)
            pb[j] = g_WoPk[(size_t)(kt * 16 + bk2[j]) * NP + n0 + bn[j]];
    };
    auto storeS = [&]() {
        #pragma unroll
        for (int j = 0; j < 8; j++) { Ah[arow[j]][ac2[j]] = pah[j]; Al[arow[j]][ac2[j]] = pal[j]; }
        #pragma unroll
        for (int j = 0; j < 8; j++) Bs[bn[j]][bk2[j]] = pb[j];
    };
    loadG(0); storeS(); __syncthreads();
    for (int kt = 0; kt < NKT; kt++) {
        if (kt + 1 < NKT) loadG(kt + 1);
        #pragma unroll
        for (int s = 0; s < 2; s++) {
            unsigned bf[4][2];
            #pragma unroll
            for (int nt = 0; nt < 4; nt++) {
                int n = warpN * 32 + nt * 8 + (lane >> 2);
                bf[nt][0] = Bs[n][(lane & 3) + s * 8];
                bf[nt][1] = Bs[n][(lane & 3) + 4 + s * 8];
            }
            #pragma unroll
            for (int mt = 0; mt < 4; mt++) {
                int r = warpM * 64 + mt * 16 + (lane >> 2);
                unsigned a0 = Ah[r][(lane & 3) + s * 8];
                unsigned a1 = Ah[r + 8][(lane & 3) + s * 8];
                unsigned a2 = Ah[r][(lane & 3) + 4 + s * 8];
                unsigned a3 = Ah[r + 8][(lane & 3) + 4 + s * 8];
                #pragma unroll
                for (int nt = 0; nt < 4; nt++)
                    mma16816(acc[mt][nt], a0, a1, a2, a3, bf[nt][0], bf[nt][1]);
                unsigned l0 = Al[r][(lane & 3) + s * 8];
                unsigned l1 = Al[r + 8][(lane & 3) + s * 8];
                unsigned l2 = Al[r][(lane & 3) + 4 + s * 8];
                unsigned l3 = Al[r + 8][(lane & 3) + 4 + s * 8];
                #pragma unroll
                for (int nt = 0; nt < 4; nt++)
                    mma16816(acc[mt][nt], l0, l1, l2, l3, bf[nt][0], bf[nt][1]);
            }
        }
        __syncthreads();
        if (kt + 1 < NKT) { storeS(); __syncthreads(); }
    }
    #pragma unroll
    for (int mt = 0; mt < 4; mt++) {
        int mrow = m0 + warpM * 64 + mt * 16 + (lane >> 2);
        #pragma unroll
        for (int half = 0; half < 2; half++) {
            int m = mrow + half * 8;
            int tt = m >> 7, bb = m & 127;
            size_t orow = ((size_t)bb * T + tt) * VV;
            #pragma unroll
            for (int nt = 0; nt < 4; nt++) {
                int n = n0 + warpN * 32 + nt * 8 + (lane & 3) * 2;
                if (n < VV)     out[orow + n]     = acc[mt][nt][half * 2]     + bias[n];
                if (n + 1 < VV) out[orow + n + 1] = acc[mt][nt][half * 2 + 1] + bias[n + 1];
            }
        }
    }
}

// ---------------- launcher --------------------------------------------------
extern "C" void kernel_launch(void* const* d_in, const int* in_sizes, int n_in,
                              void* d_out, int out_size)
{
    const int*   cap  = (const int*)  d_in[0];   // [B,T] int32
    const float* gf   = (const float*)d_in[1];   // [B,H]
    const float* area = (const float*)d_in[2];   // [B,H,F]
    const float* h0   = (const float*)d_in[3];
    const float* c0   = (const float*)d_in[4];
    const float* emb  = (const float*)d_in[5];   // [V,H]
    const float* Wih  = (const float*)d_in[6];   // [2H,4H]
    const float* Whh  = (const float*)d_in[7];   // [H,4H]
    const float* bih  = (const float*)d_in[8];
    const float* bhh  = (const float*)d_in[9];
    const float* Wv   = (const float*)d_in[10];  // [H,H]
    const float* Wh   = (const float*)d_in[11];  // [H,H]
    const float* wo   = (const float*)d_in[12];  // [H]
    const float* Wout = (const float*)d_in[13];  // [2H,V]
    const float* bout = (const float*)d_in[14];  // [V]
    float* out = (float*)d_out;

    prep_kernel<<<256, 256>>>(h0, c0);
    convW_kernel<<<(512 * NP) / 256, 256>>>(Wout);
    convWih_kernel<<<(512 * H4) / 256, 256>>>(Wih, bih, bhh);
    convWhh_kernel<<<(H * H4) / 256, 256>>>(Whh);
    gatherX_kernel<<<(MM * H2) / 256, 256>>>(cap, gf, emb);
    pgemm_kernel<<<dim3(16, 20), 256>>>();
    vproj_kernel<<<dim3(8, 98), 256>>>(area, Wv);
    loop_kernel<<<128, 256>>>(Wh, wo, area);
    final_mma_kernel<<<dim3(79, 20), 256>>>(bout, out);
}

// round 9
// speedup vs baseline: 1.8845x; 1.0315x over previous
#include <cuda_runtime.h>
#include <cuda_fp16.h>
#include <cstdint>
#include <math.h>

// Problem constants
#define B 128
#define T 20
#define VV 10000
#define H 512
#define F 49
// derived
#define H2 1024   // 2H
#define H4 2048   // 4H
#define HF 25088  // H*F
#define NP 10112  // padded vocab (79*128)
#define MM (T*B)  // 2560 rows of P / X

// ---------------- scratch (device globals; no allocation allowed) ----------
__device__ float g_Vproj[B * F * H];        // [B,F,H]
__device__ float g_hA[B * H];
__device__ float g_hB[B * H];
__device__ float g_c[B * H];
__device__ float g_hw[B * H];
__device__ float g_P[MM * H4];              // precomputed input gates (permuted cols)
__device__ float g_biasP[H4];               // permuted bias
__device__ float g_Whh_p[H * H4];           // [512, 2048] permuted Whh
// fp16 split buffers (packed B words: (k,k+1) pair per 32-bit word)
__device__ unsigned g_WoPk[512 * NP];       // W_out hi, packed [k2][n]
__device__ unsigned g_WihPkHi[512 * H4];    // Wih permuted hi, packed [k2][p]
__device__ unsigned g_WihPkLo[512 * H4];
__device__ __half g_Xhi[MM * H2];
__device__ __half g_Xlo[MM * H2];
__device__ __half g_Phi[MM * H2];           // [emb|gf] rows
__device__ __half g_Plo[MM * H2];

__device__ __forceinline__ float fast_tanh(float x)
{
    float e = __expf(2.f * x);
    return 1.f - __fdividef(2.f, e + 1.f);
}
__device__ __forceinline__ float fast_sig(float x)
{
    return __fdividef(1.f, 1.f + __expf(-x));
}

// ---------------- prep: h,c <- h0,c0 ----------------------------------------
__global__ void prep_kernel(const float* __restrict__ h0, const float* __restrict__ c0)
{
    int idx = blockIdx.x * blockDim.x + threadIdx.x;   // 65536
    g_hA[idx] = h0[idx];
    g_c[idx]  = c0[idx];
}

// ---------------- W_out -> fp16 hi packed words, zero-padded to NP ----------
__global__ void convW_kernel(const float* __restrict__ W)
{
    int idx = blockIdx.x * blockDim.x + threadIdx.x;   // 512*NP
    int k2 = idx / NP, n = idx - k2 * NP;
    float v0 = 0.f, v1 = 0.f;
    if (n < VV) {
        v0 = W[(size_t)(2 * k2) * VV + n];
        v1 = W[(size_t)(2 * k2 + 1) * VV + n];
    }
    unsigned lo = __half_as_ushort(__float2half_rn(v0));
    unsigned hi = __half_as_ushort(__float2half_rn(v1));
    g_WoPk[idx] = lo | (hi << 16);
}

// ---------------- W_ih permuted -> fp16 hi/lo packed + biasP ----------------
// permuted col p: hh=p/4, q=p%4 -> orig col q*512+hh  (gate order i,f,g,o)
__global__ void convWih_kernel(const float* __restrict__ Wih,
                               const float* __restrict__ bih, const float* __restrict__ bhh)
{
    int idx = blockIdx.x * blockDim.x + threadIdx.x;   // 512*2048
    int k2 = idx >> 11, p = idx & 2047;
    int hh = p >> 2, q = p & 3;
    int n = q * 512 + hh;
    float v0 = Wih[(size_t)(2 * k2) * H4 + n];
    float v1 = Wih[(size_t)(2 * k2 + 1) * H4 + n];
    __half h0 = __float2half_rn(v0);
    __half h1 = __float2half_rn(v1);
    float r0 = v0 - __half2float(h0);
    float r1 = v1 - __half2float(h1);
    g_WihPkHi[idx] = (unsigned)__half_as_ushort(h0) |
                     ((unsigned)__half_as_ushort(h1) << 16);
    g_WihPkLo[idx] = (unsigned)__half_as_ushort(__float2half_rn(r0)) |
                     ((unsigned)__half_as_ushort(__float2half_rn(r1)) << 16);
    if (k2 == 0) g_biasP[p] = bih[n] + bhh[n];
}

// ---------------- build Whh permuted fp32 -----------------------------------
__global__ void convWhh_kernel(const float* __restrict__ Whh)
{
    int idx = blockIdx.x * blockDim.x + threadIdx.x;   // 512*2048
    int k = idx >> 11, p = idx & 2047;
    int hh = p >> 2, q = p & 3;
    g_Whh_p[idx] = Whh[(size_t)k * H4 + q * 512 + hh];
}

// ---------------- gather [emb|gf] rows -> fp16 hi/lo ------------------------
__global__ void gatherX_kernel(const int* __restrict__ cap, const float* __restrict__ gf,
                               const float* __restrict__ emb)
{
    int idx = blockIdx.x * blockDim.x + threadIdx.x;   // MM*1024
    int m = idx >> 10, k = idx & 1023;
    int bb = m & 127, tt = m >> 7;
    float v;
    if (k < 512) {
        int tok = cap[bb * T + tt];
        v = emb[(size_t)tok * H + k];
    } else {
        v = gf[(size_t)bb * H + (k - 512)];
    }
    __half hi = __float2half_rn(v);
    g_Phi[idx] = hi;
    g_Plo[idx] = __float2half_rn(v - __half2float(hi));
}

// ---------------- Vproj = swap(area) @ Wv : [6272,512] @ [512,512] ----------
__global__ void vproj_kernel(const float* __restrict__ area, const float* __restrict__ Wv)
{
    __shared__ float As[16][66];
    __shared__ float Bs[16][66];
    int tid = threadIdx.x;                 // 256
    int n0 = blockIdx.x * 64;              // 8 blocks
    int m0 = blockIdx.y * 64;              // 98 blocks
    int tm = (tid >> 4) * 4;
    int tn = (tid & 15) * 4;
    float acc[4][4] = {};
    for (int k0 = 0; k0 < H; k0 += 16) {
        #pragma unroll
        for (int i = 0; i < 4; i++) {
            int idx = tid + i * 256;
            int kk = idx >> 6, mm = idx & 63;
            int m = m0 + mm;
            int bb = m / 49, ff = m % 49;
            As[kk][mm] = area[(size_t)bb * HF + (size_t)(k0 + kk) * 49 + ff];
        }
        #pragma unroll
        for (int i = 0; i < 4; i++) {
            int idx = tid + i * 256;
            int kk = idx >> 6, nn = idx & 63;
            Bs[kk][nn] = Wv[(size_t)(k0 + kk) * H + n0 + nn];
        }
        __syncthreads();
        #pragma unroll
        for (int k = 0; k < 16; k++) {
            float a[4], bb2[4];
            #pragma unroll
            for (int i = 0; i < 4; i++) a[i] = As[k][tm + i];
            #pragma unroll
            for (int j = 0; j < 4; j++) bb2[j] = Bs[k][tn + j];
            #pragma unroll
            for (int i = 0; i < 4; i++)
                #pragma unroll
                for (int j = 0; j < 4; j++)
                    acc[i][j] += a[i] * bb2[j];
        }
        __syncthreads();
    }
    #pragma unroll
    for (int i = 0; i < 4; i++)
        #pragma unroll
        for (int j = 0; j < 4; j++)
            g_Vproj[(size_t)(m0 + tm + i) * H + n0 + tn + j] = acc[i][j];
}

// ---------------- fp16 MMA helper -------------------------------------------
__device__ __forceinline__ void mma16816(float* d, unsigned a0, unsigned a1,
                                         unsigned a2, unsigned a3,
                                         unsigned b0, unsigned b1)
{
    asm volatile(
        "mma.sync.aligned.m16n8k16.row.col.f32.f16.f16.f32 "
        "{%0,%1,%2,%3}, {%4,%5,%6,%7}, {%8,%9}, {%0,%1,%2,%3};\n"
        : "+f"(d[0]), "+f"(d[1]), "+f"(d[2]), "+f"(d[3])
        : "r"(a0), "r"(a1), "r"(a2), "r"(a3), "r"(b0), "r"(b1));
}

// ---------------- P = [emb|gf] @ Wih_perm + biasP (fp16x3, B-reuse) ---------
__global__ __launch_bounds__(256) void pgemm_kernel()
{
    __shared__ unsigned Ah[128][17];   // [row][c2]
    __shared__ unsigned Al[128][17];
    __shared__ unsigned Bh[128][17];   // [n][k2]
    __shared__ unsigned Bl[128][17];
    int tid = threadIdx.x;
    int lane = tid & 31, warp = tid >> 5;
    int warpM = warp >> 2, warpN = warp & 3;
    int n0 = blockIdx.x * 128;                        // 16 blocks
    int m0 = blockIdx.y * 128;                        // 20 blocks
    float acc[4][4][4];
    #pragma unroll
    for (int i = 0; i < 4; i++)
        #pragma unroll
        for (int j = 0; j < 4; j++)
            #pragma unroll
            for (int q = 0; q < 4; q++) acc[i][j][q] = 0.f;

    unsigned pah[8], pal[8], pbh[8], pbl[8];
    const int NKT = 32;
    int arow[8], ac2[8], bn[8], bk2[8];
    #pragma unroll
    for (int j = 0; j < 8; j++) {
        int i = tid + j * 256;
        arow[j] = i >> 4;  ac2[j] = i & 15;
        bn[j] = i & 127;   bk2[j] = i >> 7;
    }
    auto loadG = [&](int kt) {
        int kk0 = kt * 32;
        #pragma unroll
        for (int j = 0; j < 8; j++) {
            size_t ao = (size_t)(m0 + arow[j]) * H2 + kk0 + ac2[j] * 2;
            pah[j] = *(const unsigned*)(g_Phi + ao);
            pal[j] = *(const unsigned*)(g_Plo + ao);
        }
        #pragma unroll
        for (int j = 0; j < 8; j++) {
            size_t bo = (size_t)(kt * 16 + bk2[j]) * H4 + n0 + bn[j];
            pbh[j] = g_WihPkHi[bo];
            pbl[j] = g_WihPkLo[bo];
        }
    };
    auto storeS = [&]() {
        #pragma unroll
        for (int j = 0; j < 8; j++) { Ah[arow[j]][ac2[j]] = pah[j]; Al[arow[j]][ac2[j]] = pal[j]; }
        #pragma unroll
        for (int j = 0; j < 8; j++) { Bh[bn[j]][bk2[j]] = pbh[j]; Bl[bn[j]][bk2[j]] = pbl[j]; }
    };
    loadG(0); storeS(); __syncthreads();
    for (int kt = 0; kt < NKT; kt++) {
        if (kt + 1 < NKT) loadG(kt + 1);
        #pragma unroll
        for (int s = 0; s < 2; s++) {
            unsigned bfh[4][2], bfl[4][2];
            #pragma unroll
            for (int nt = 0; nt < 4; nt++) {
                int n = warpN * 32 + nt * 8 + (lane >> 2);
                bfh[nt][0] = Bh[n][(lane & 3) + s * 8];
                bfh[nt][1] = Bh[n][(lane & 3) + 4 + s * 8];
                bfl[nt][0] = Bl[n][(lane & 3) + s * 8];
                bfl[nt][1] = Bl[n][(lane & 3) + 4 + s * 8];
            }
            #pragma unroll
            for (int mt = 0; mt < 4; mt++) {
                int r = warpM * 64 + mt * 16 + (lane >> 2);
                unsigned a0 = Ah[r][(lane & 3) + s * 8];
                unsigned a1 = Ah[r + 8][(lane & 3) + s * 8];
                unsigned a2 = Ah[r][(lane & 3) + 4 + s * 8];
                unsigned a3 = Ah[r + 8][(lane & 3) + 4 + s * 8];
                #pragma unroll
                for (int nt = 0; nt < 4; nt++)
                    mma16816(acc[mt][nt], a0, a1, a2, a3, bfh[nt][0], bfh[nt][1]);
                #pragma unroll
                for (int nt = 0; nt < 4; nt++)
                    mma16816(acc[mt][nt], a0, a1, a2, a3, bfl[nt][0], bfl[nt][1]);
                unsigned l0 = Al[r][(lane & 3) + s * 8];
                unsigned l1 = Al[r + 8][(lane & 3) + s * 8];
                unsigned l2 = Al[r][(lane & 3) + 4 + s * 8];
                unsigned l3 = Al[r + 8][(lane & 3) + 4 + s * 8];
                #pragma unroll
                for (int nt = 0; nt < 4; nt++)
                    mma16816(acc[mt][nt], l0, l1, l2, l3, bfh[nt][0], bfh[nt][1]);
            }
        }
        __syncthreads();
        if (kt + 1 < NKT) { storeS(); __syncthreads(); }
    }
    #pragma unroll
    for (int mt = 0; mt < 4; mt++) {
        int mrow = m0 + warpM * 64 + mt * 16 + (lane >> 2);
        #pragma unroll
        for (int half = 0; half < 2; half++) {
            int m = mrow + half * 8;
            #pragma unroll
            for (int nt = 0; nt < 4; nt++) {
                int n = n0 + warpN * 32 + nt * 8 + (lane & 3) * 2;
                g_P[(size_t)m * H4 + n]     = acc[mt][nt][half * 2]     + g_biasP[n];
                g_P[(size_t)m * H4 + n + 1] = acc[mt][nt][half * 2 + 1] + g_biasP[n + 1];
            }
        }
    }
}

// ---------------- per-step: gates = h @ Whh_p ; LSTM epilogue ---------------
__global__ __launch_bounds__(256) void step_kernel(int t)
{
    __shared__ float As[16][34];           // [k][m]
    __shared__ float Bs[16][66];           // [k][n]
    const float* hs = (t & 1) ? g_hB : g_hA;
    float* hd       = (t & 1) ? g_hA : g_hB;
    int tid = threadIdx.x;
    int n0 = blockIdx.x * 64;
    int m0 = blockIdx.y * 32;
    int ty = tid >> 4, tx = tid & 15;
    int tm = ty * 2;
    int tn = tx * 4;
    float acc[2][4] = {};
    for (int k0 = 0; k0 < H; k0 += 16) {
        #pragma unroll
        for (int i = 0; i < 2; i++) {
            int idx = tid + i * 256;
            int kk = idx >> 5, mm = idx & 31;
            As[kk][mm] = hs[(size_t)(m0 + mm) * H + k0 + kk];
        }
        #pragma unroll
        for (int i = 0; i < 4; i++) {
            int idx = tid + i * 256;
            int kk = idx >> 6, nn = idx & 63;
            Bs[kk][nn] = g_Whh_p[(size_t)(k0 + kk) * H4 + n0 + nn];
        }
        __syncthreads();
        #pragma unroll
        for (int k = 0; k < 16; k++) {
            float a0 = As[k][tm], a1 = As[k][tm + 1];
            float b0 = Bs[k][tn], b1 = Bs[k][tn + 1];
            float b2 = Bs[k][tn + 2], b3 = Bs[k][tn + 3];
            acc[0][0] += a0 * b0; acc[0][1] += a0 * b1;
            acc[0][2] += a0 * b2; acc[0][3] += a0 * b3;
            acc[1][0] += a1 * b0; acc[1][1] += a1 * b1;
            acc[1][2] += a1 * b2; acc[1][3] += a1 * b3;
        }
        __syncthreads();
    }
    int hh = (n0 + tn) >> 2;
    #pragma unroll
    for (int i = 0; i < 2; i++) {
        int m = m0 + tm + i;
        const float* Pr = g_P + (size_t)(t * B + m) * H4 + n0 + tn;
        float gi = acc[i][0] + Pr[0];
        float gf = acc[i][1] + Pr[1];
        float gg = acc[i][2] + Pr[2];
        float go = acc[i][3] + Pr[3];
        float si = fast_sig(gi);
        float sf = fast_sig(gf);
        float so = fast_sig(go);
        int idx = m * H + hh;
        float c = sf * g_c[idx] + si * fast_tanh(gg);
        float h = so * fast_tanh(c);
        g_c[idx] = c;
        hd[idx] = h;
        int xi = (t * B + m) * H2 + hh;
        __half hhi = __float2half_rn(h);
        g_Xhi[xi] = hhi;
        g_Xlo[xi] = __float2half_rn(h - __half2float(hhi));
    }
}

// ---------------- hw = h_new @ Wh : [128,512] @ [512,512] -------------------
__global__ void hw_kernel(const float* __restrict__ Wh, int t)
{
    __shared__ float As[16][18];
    __shared__ float Bs[16][66];
    const float* hsrc = (t & 1) ? g_hA : g_hB;   // NEW h written by step_kernel
    int tid = threadIdx.x;
    int n0 = blockIdx.x * 64;
    int m0 = blockIdx.y * 16;
    int r  = tid >> 4;
    int tn = (tid & 15) * 4;
    float acc[4] = {};
    for (int k0 = 0; k0 < H; k0 += 16) {
        {
            int mm = tid >> 4, kk = tid & 15;
            As[mm][kk] = hsrc[(size_t)(m0 + mm) * H + k0 + kk];
        }
        #pragma unroll
        for (int i = 0; i < 4; i++) {
            int idx = tid + i * 256;
            int kk = idx >> 6, nn = idx & 63;
            Bs[kk][nn] = Wh[(size_t)(k0 + kk) * H + n0 + nn];
        }
        __syncthreads();
        #pragma unroll
        for (int k = 0; k < 16; k++) {
            float a = As[r][k];
            acc[0] += a * Bs[k][tn];
            acc[1] += a * Bs[k][tn + 1];
            acc[2] += a * Bs[k][tn + 2];
            acc[3] += a * Bs[k][tn + 3];
        }
        __syncthreads();
    }
    #pragma unroll
    for (int j = 0; j < 4; j++)
        g_hw[(size_t)(m0 + r) * H + n0 + tn + j] = acc[j];
}

// ---------------- attention: scores, softmax, attended -> Xhi/Xlo -----------
__global__ void attn_kernel(const float* __restrict__ wo, const float* __restrict__ area, int t)
{
    int bb = blockIdx.x, tid = threadIdx.x;   // 128 blocks x 256
    __shared__ float shw[512];
    __shared__ float swo[512];
    __shared__ float sal[52];
    shw[tid]       = g_hw[(size_t)bb * H + tid];
    shw[tid + 256] = g_hw[(size_t)bb * H + tid + 256];
    swo[tid]       = wo[tid];
    swo[tid + 256] = wo[tid + 256];
    __syncthreads();
    int warp = tid >> 5, lane = tid & 31;
    for (int f = warp; f < F; f += 8) {
        const float* vp = g_Vproj + ((size_t)bb * F + f) * H;
        float s = 0.f;
        for (int k = lane; k < H; k += 32)
            s += swo[k] * fast_tanh(vp[k] + shw[k]);
        #pragma unroll
        for (int off = 16; off; off >>= 1)
            s += __shfl_xor_sync(0xffffffffu, s, off);
        if (lane == 0) sal[f] = s;
    }
    __syncthreads();
    if (tid < 32) {
        float v0 = (tid < F) ? sal[tid] : -3.4e38f;
        float v1 = (tid + 32 < F) ? sal[tid + 32] : -3.4e38f;
        float mx = fmaxf(v0, v1);
        #pragma unroll
        for (int off = 16; off; off >>= 1)
            mx = fmaxf(mx, __shfl_xor_sync(0xffffffffu, mx, off));
        float e0 = (tid < F) ? __expf(v0 - mx) : 0.f;
        float e1 = (tid + 32 < F) ? __expf(v1 - mx) : 0.f;
        float s = e0 + e1;
        #pragma unroll
        for (int off = 16; off; off >>= 1)
            s += __shfl_xor_sync(0xffffffffu, s, off);
        float inv = __fdividef(1.f, s);
        if (tid < F) sal[tid] = e0 * inv;
        if (tid + 32 < F) sal[tid + 32] = e1 * inv;
    }
    __syncthreads();
    for (int h = tid; h < H; h += 256) {
        const float* ar = area + ((size_t)bb * H + h) * F;
        float s = 0.f;
        #pragma unroll
        for (int f = 0; f < F; f++) s += ar[f] * sal[f];
        int xi = (t * B + bb) * H2 + H + h;
        __half shi = __float2half_rn(s);
        g_Xhi[xi] = shi;
        g_Xlo[xi] = __float2half_rn(s - __half2float(shi));
    }
}

// ---------------- final slice: out rows of one t (fp16x2, B-reuse) ----------
__global__ __launch_bounds__(256) void final_slice_kernel(const float* __restrict__ bias,
                                                          float* __restrict__ out, int m0)
{
    __shared__ unsigned Ah[128][17];
    __shared__ unsigned Al[128][17];
    __shared__ unsigned Bs[128][17];
    int tid = threadIdx.x;
    int lane = tid & 31, warp = tid >> 5;
    int warpM = warp >> 2, warpN = warp & 3;
    int n0 = blockIdx.x * 128;                        // 79 blocks
    float acc[4][4][4];
    #pragma unroll
    for (int i = 0; i < 4; i++)
        #pragma unroll
        for (int j = 0; j < 4; j++)
            #pragma unroll
            for (int q = 0; q < 4; q++) acc[i][j][q] = 0.f;

    unsigned pah[8], pal[8], pb[8];
    const int NKT = 32;
    int arow[8], ac2[8], bn[8], bk2[8];
    #pragma unroll
    for (int j = 0; j < 8; j++) {
        int i = tid + j * 256;
        arow[j] = i >> 4;  ac2[j] = i & 15;
        bn[j] = i & 127;   bk2[j] = i >> 7;
    }
    auto loadG = [&](int kt) {
        int kk0 = kt * 32;
        #pragma unroll
        for (int j = 0; j < 8; j++) {
            size_t ao = (size_t)(m0 + arow[j]) * H2 + kk0 + ac2[j] * 2;
            pah[j] = *(const unsigned*)(g_Xhi + ao);
            pal[j] = *(const unsigned*)(g_Xlo + ao);
        }
        #pragma unroll
        for (int j = 0; j < 8; j++)
            pb[j] = g_WoPk[(size_t)(kt * 16 + bk2[j]) * NP + n0 + bn[j]];
    };
    auto storeS = [&]() {
        #pragma unroll
        for (int j = 0; j < 8; j++) { Ah[arow[j]][ac2[j]] = pah[j]; Al[arow[j]][ac2[j]] = pal[j]; }
        #pragma unroll
        for (int j = 0; j < 8; j++) Bs[bn[j]][bk2[j]] = pb[j];
    };
    loadG(0); storeS(); __syncthreads();
    for (int kt = 0; kt < NKT; kt++) {
        if (kt + 1 < NKT) loadG(kt + 1);
        #pragma unroll
        for (int s = 0; s < 2; s++) {
            unsigned bf[4][2];
            #pragma unroll
            for (int nt = 0; nt < 4; nt++) {
                int n = warpN * 32 + nt * 8 + (lane >> 2);
                bf[nt][0] = Bs[n][(lane & 3) + s * 8];
                bf[nt][1] = Bs[n][(lane & 3) + 4 + s * 8];
            }
            #pragma unroll
            for (int mt = 0; mt < 4; mt++) {
                int r = warpM * 64 + mt * 16 + (lane >> 2);
                unsigned a0 = Ah[r][(lane & 3) + s * 8];
                unsigned a1 = Ah[r + 8][(lane & 3) + s * 8];
                unsigned a2 = Ah[r][(lane & 3) + 4 + s * 8];
                unsigned a3 = Ah[r + 8][(lane & 3) + 4 + s * 8];
                #pragma unroll
                for (int nt = 0; nt < 4; nt++)
                    mma16816(acc[mt][nt], a0, a1, a2, a3, bf[nt][0], bf[nt][1]);
                unsigned l0 = Al[r][(lane & 3) + s * 8];
                unsigned l1 = Al[r + 8][(lane & 3) + s * 8];
                unsigned l2 = Al[r][(lane & 3) + 4 + s * 8];
                unsigned l3 = Al[r + 8][(lane & 3) + 4 + s * 8];
                #pragma unroll
                for (int nt = 0; nt < 4; nt++)
                    mma16816(acc[mt][nt], l0, l1, l2, l3, bf[nt][0], bf[nt][1]);
            }
        }
        __syncthreads();
        if (kt + 1 < NKT) { storeS(); __syncthreads(); }
    }
    #pragma unroll
    for (int mt = 0; mt < 4; mt++) {
        int mrow = m0 + warpM * 64 + mt * 16 + (lane >> 2);
        #pragma unroll
        for (int half = 0; half < 2; half++) {
            int m = mrow + half * 8;
            int tt = m >> 7, bb = m & 127;
            size_t orow = ((size_t)bb * T + tt) * VV;
            #pragma unroll
            for (int nt = 0; nt < 4; nt++) {
                int n = n0 + warpN * 32 + nt * 8 + (lane & 3) * 2;
                if (n < VV)     out[orow + n]     = acc[mt][nt][half * 2]     + bias[n];
                if (n + 1 < VV) out[orow + n + 1] = acc[mt][nt][half * 2 + 1] + bias[n + 1];
            }
        }
    }
}

// ---------------- launcher (stream-forked DAG) ------------------------------
extern "C" void kernel_launch(void* const* d_in, const int* in_sizes, int n_in,
                              void* d_out, int out_size)
{
    const int*   cap  = (const int*)  d_in[0];   // [B,T] int32
    const float* gf   = (const float*)d_in[1];   // [B,H]
    const float* area = (const float*)d_in[2];   // [B,H,F]
    const float* h0   = (const float*)d_in[3];
    const float* c0   = (const float*)d_in[4];
    const float* emb  = (const float*)d_in[5];   // [V,H]
    const float* Wih  = (const float*)d_in[6];   // [2H,4H]
    const float* Whh  = (const float*)d_in[7];   // [H,4H]
    const float* bih  = (const float*)d_in[8];
    const float* bhh  = (const float*)d_in[9];
    const float* Wv   = (const float*)d_in[10];  // [H,H]
    const float* Wh   = (const float*)d_in[11];  // [H,H]
    const float* wo   = (const float*)d_in[12];  // [H]
    const float* Wout = (const float*)d_in[13];  // [2H,V]
    const float* bout = (const float*)d_in[14];  // [V]
    float* out = (float*)d_out;

    static cudaStream_t s1 = 0, s2 = 0;
    static cudaEvent_t evFork, evW, evPre, evT[T], evS1, evS2;
    static int inited = 0;
    if (!inited) {
        cudaStreamCreateWithFlags(&s1, cudaStreamNonBlocking);
        cudaStreamCreateWithFlags(&s2, cudaStreamNonBlocking);
        cudaEventCreateWithFlags(&evFork, cudaEventDisableTiming);
        cudaEventCreateWithFlags(&evW,    cudaEventDisableTiming);
        cudaEventCreateWithFlags(&evPre,  cudaEventDisableTiming);
        cudaEventCreateWithFlags(&evS1,   cudaEventDisableTiming);
        cudaEventCreateWithFlags(&evS2,   cudaEventDisableTiming);
        for (int t = 0; t < T; t++)
            cudaEventCreateWithFlags(&evT[t], cudaEventDisableTiming);
        inited = 1;
    }
    cudaStream_t s0 = 0;   // harness stream (default)

    // fork side streams off the capture stream
    cudaEventRecord(evFork, s0);
    cudaStreamWaitEvent(s1, evFork, 0);
    cudaStreamWaitEvent(s2, evFork, 0);

    // s1: W_out conversion + Vproj (independent of recurrence prolog)
    convW_kernel<<<(512 * NP) / 256, 256, 0, s1>>>(Wout);
    cudaEventRecord(evW, s1);              // slices on s2 need convW
    vproj_kernel<<<dim3(8, 98), 256, 0, s1>>>(area, Wv);
    cudaEventRecord(evPre, s1);            // attn needs vproj
    cudaStreamWaitEvent(s2, evW, 0);

    // s0: recurrence prolog
    prep_kernel<<<256, 256, 0, s0>>>(h0, c0);
    convWih_kernel<<<(512 * H4) / 256, 256, 0, s0>>>(Wih, bih, bhh);
    convWhh_kernel<<<(H * H4) / 256, 256, 0, s0>>>(Whh);
    gatherX_kernel<<<(MM * H2) / 256, 256, 0, s0>>>(cap, gf, emb);
    pgemm_kernel<<<dim3(16, 20), 256, 0, s0>>>();
    cudaStreamWaitEvent(s0, evPre, 0);     // vproj ready before attention

    // recurrence loop with final-GEMM slices overlapped on s1/s2
    for (int t = 0; t < T; t++) {
        step_kernel<<<dim3(32, 4), 256, 0, s0>>>(t);
        hw_kernel<<<dim3(8, 8), 256, 0, s0>>>(Wh, t);
        attn_kernel<<<128, 256, 0, s0>>>(wo, area, t);
        cudaEventRecord(evT[t], s0);
        cudaStream_t ss = (t & 1) ? s2 : s1;
        cudaStreamWaitEvent(ss, evT[t], 0);
        final_slice_kernel<<<79, 256, 0, ss>>>(bout, out, t * B);
    }

    // join side streams back into s0
    cudaEventRecord(evS1, s1);
    cudaEventRecord(evS2, s2);
    cudaStreamWaitEvent(s0, evS1, 0);
    cudaStreamWaitEvent(s0, evS2, 0);
}

// round 17
// speedup vs baseline: 1.9175x; 1.0175x over previous
#include <cuda_runtime.h>
#include <cuda_fp16.h>
#include <cstdint>
#include <math.h>

// Problem constants
#define B 128
#define T 20
#define VV 10000
#define H 512
#define F 49
// derived
#define H2 1024   // 2H
#define H4 2048   // 4H
#define HF 25088  // H*F
#define NP 10112  // padded vocab (79*128)
#define MM (T*B)  // 2560 rows of P / X

// ---------------- scratch (device globals; no allocation allowed) ----------
__device__ float g_Vproj[B * F * H];        // [B,F,H]
__device__ float g_hA[B * H];
__device__ float g_hB[B * H];
__device__ float g_c[B * H];
__device__ float g_hw[B * H];
__device__ float g_P[MM * H4];              // precomputed input gates (permuted cols)
__device__ float g_biasP[H4];               // permuted bias
__device__ float g_Whh_p[H * H4];           // [512, 2048] permuted Whh
// fp16 buffers (packed B words: (k,k+1) pair per 32-bit word)
__device__ unsigned g_WoPk[512 * NP];       // W_out hi, packed [k2][n]
__device__ unsigned g_WihPkHi[512 * H4];    // Wih permuted hi, packed [k2][p]
__device__ unsigned g_WihPkLo[512 * H4];
__device__ __half g_Xhi[MM * H2];
__device__ __half g_Phi[MM * H2];           // [emb|gf] rows
__device__ __half g_Plo[MM * H2];

__device__ __forceinline__ float fast_tanh(float x)
{
    float e = __expf(2.f * x);
    return 1.f - __fdividef(2.f, e + 1.f);
}
__device__ __forceinline__ float fast_sig(float x)
{
    return __fdividef(1.f, 1.f + __expf(-x));
}

// ---------------- prep: h,c <- h0,c0 ----------------------------------------
__global__ void prep_kernel(const float* __restrict__ h0, const float* __restrict__ c0)
{
    int idx = blockIdx.x * blockDim.x + threadIdx.x;   // 65536
    g_hA[idx] = h0[idx];
    g_c[idx]  = c0[idx];
}

// ---------------- W_out -> fp16 hi packed words, zero-padded to NP ----------
__global__ void convW_kernel(const float* __restrict__ W)
{
    int idx = blockIdx.x * blockDim.x + threadIdx.x;   // 512*NP
    int k2 = idx / NP, n = idx - k2 * NP;
    float v0 = 0.f, v1 = 0.f;
    if (n < VV) {
        v0 = W[(size_t)(2 * k2) * VV + n];
        v1 = W[(size_t)(2 * k2 + 1) * VV + n];
    }
    unsigned lo = __half_as_ushort(__float2half_rn(v0));
    unsigned hi = __half_as_ushort(__float2half_rn(v1));
    g_WoPk[idx] = lo | (hi << 16);
}

// ---------------- W_ih permuted -> fp16 hi/lo packed + biasP ----------------
// permuted col p: hh=p/4, q=p%4 -> orig col q*512+hh  (gate order i,f,g,o)
__global__ void convWih_kernel(const float* __restrict__ Wih,
                               const float* __restrict__ bih, const float* __restrict__ bhh)
{
    int idx = blockIdx.x * blockDim.x + threadIdx.x;   // 512*2048
    int k2 = idx >> 11, p = idx & 2047;
    int hh = p >> 2, q = p & 3;
    int n = q * 512 + hh;
    float v0 = Wih[(size_t)(2 * k2) * H4 + n];
    float v1 = Wih[(size_t)(2 * k2 + 1) * H4 + n];
    __half h0 = __float2half_rn(v0);
    __half h1 = __float2half_rn(v1);
    float r0 = v0 - __half2float(h0);
    float r1 = v1 - __half2float(h1);
    g_WihPkHi[idx] = (unsigned)__half_as_ushort(h0) |
                     ((unsigned)__half_as_ushort(h1) << 16);
    g_WihPkLo[idx] = (unsigned)__half_as_ushort(__float2half_rn(r0)) |
                     ((unsigned)__half_as_ushort(__float2half_rn(r1)) << 16);
    if (k2 == 0) g_biasP[p] = bih[n] + bhh[n];
}

// ---------------- build Whh permuted fp32 -----------------------------------
__global__ void convWhh_kernel(const float* __restrict__ Whh)
{
    int idx = blockIdx.x * blockDim.x + threadIdx.x;   // 512*2048
    int k = idx >> 11, p = idx & 2047;
    int hh = p >> 2, q = p & 3;
    g_Whh_p[idx] = Whh[(size_t)k * H4 + q * 512 + hh];
}

// ---------------- gather [emb|gf] rows -> fp16 hi/lo ------------------------
__global__ void gatherX_kernel(const int* __restrict__ cap, const float* __restrict__ gf,
                               const float* __restrict__ emb)
{
    int idx = blockIdx.x * blockDim.x + threadIdx.x;   // MM*1024
    int m = idx >> 10, k = idx & 1023;
    int bb = m & 127, tt = m >> 7;
    float v;
    if (k < 512) {
        int tok = cap[bb * T + tt];
        v = emb[(size_t)tok * H + k];
    } else {
        v = gf[(size_t)bb * H + (k - 512)];
    }
    __half hi = __float2half_rn(v);
    g_Phi[idx] = hi;
    g_Plo[idx] = __float2half_rn(v - __half2float(hi));
}

// ---------------- Vproj = swap(area) @ Wv : [6272,512] @ [512,512] ----------
__global__ void vproj_kernel(const float* __restrict__ area, const float* __restrict__ Wv)
{
    __shared__ float As[16][66];
    __shared__ float Bs[16][66];
    int tid = threadIdx.x;                 // 256
    int n0 = blockIdx.x * 64;              // 8 blocks
    int m0 = blockIdx.y * 64;              // 98 blocks
    int tm = (tid >> 4) * 4;
    int tn = (tid & 15) * 4;
    float acc[4][4] = {};
    for (int k0 = 0; k0 < H; k0 += 16) {
        #pragma unroll
        for (int i = 0; i < 4; i++) {
            int idx = tid + i * 256;
            int kk = idx >> 6, mm = idx & 63;
            int m = m0 + mm;
            int bb = m / 49, ff = m % 49;
            As[kk][mm] = area[(size_t)bb * HF + (size_t)(k0 + kk) * 49 + ff];
        }
        #pragma unroll
        for (int i = 0; i < 4; i++) {
            int idx = tid + i * 256;
            int kk = idx >> 6, nn = idx & 63;
            Bs[kk][nn] = Wv[(size_t)(k0 + kk) * H + n0 + nn];
        }
        __syncthreads();
        #pragma unroll
        for (int k = 0; k < 16; k++) {
            float a[4], bb2[4];
            #pragma unroll
            for (int i = 0; i < 4; i++) a[i] = As[k][tm + i];
            #pragma unroll
            for (int j = 0; j < 4; j++) bb2[j] = Bs[k][tn + j];
            #pragma unroll
            for (int i = 0; i < 4; i++)
                #pragma unroll
                for (int j = 0; j < 4; j++)
                    acc[i][j] += a[i] * bb2[j];
        }
        __syncthreads();
    }
    #pragma unroll
    for (int i = 0; i < 4; i++)
        #pragma unroll
        for (int j = 0; j < 4; j++)
            g_Vproj[(size_t)(m0 + tm + i) * H + n0 + tn + j] = acc[i][j];
}

// ---------------- fp16 MMA helper -------------------------------------------
__device__ __forceinline__ void mma16816(float* d, unsigned a0, unsigned a1,
                                         unsigned a2, unsigned a3,
                                         unsigned b0, unsigned b1)
{
    asm volatile(
        "mma.sync.aligned.m16n8k16.row.col.f32.f16.f16.f32 "
        "{%0,%1,%2,%3}, {%4,%5,%6,%7}, {%8,%9}, {%0,%1,%2,%3};\n"
        : "+f"(d[0]), "+f"(d[1]), "+f"(d[2]), "+f"(d[3])
        : "r"(a0), "r"(a1), "r"(a2), "r"(a3), "r"(b0), "r"(b1));
}

// ---------------- P = [emb|gf] @ Wih_perm + biasP (fp16x3, B-reuse) ---------
__global__ __launch_bounds__(256) void pgemm_kernel()
{
    __shared__ unsigned Ah[128][17];   // [row][c2]
    __shared__ unsigned Al[128][17];
    __shared__ unsigned Bh[128][17];   // [n][k2]
    __shared__ unsigned Bl[128][17];
    int tid = threadIdx.x;
    int lane = tid & 31, warp = tid >> 5;
    int warpM = warp >> 2, warpN = warp & 3;
    int n0 = blockIdx.x * 128;                        // 16 blocks
    int m0 = blockIdx.y * 128;                        // 20 blocks
    float acc[4][4][4];
    #pragma unroll
    for (int i = 0; i < 4; i++)
        #pragma unroll
        for (int j = 0; j < 4; j++)
            #pragma unroll
            for (int q = 0; q < 4; q++) acc[i][j][q] = 0.f;

    unsigned pah[8], pal[8], pbh[8], pbl[8];
    const int NKT = 32;
    int arow[8], ac2[8], bn[8], bk2[8];
    #pragma unroll
    for (int j = 0; j < 8; j++) {
        int i = tid + j * 256;
        arow[j] = i >> 4;  ac2[j] = i & 15;
        bn[j] = i & 127;   bk2[j] = i >> 7;
    }
    auto loadG = [&](int kt) {
        int kk0 = kt * 32;
        #pragma unroll
        for (int j = 0; j < 8; j++) {
            size_t ao = (size_t)(m0 + arow[j]) * H2 + kk0 + ac2[j] * 2;
            pah[j] = *(const unsigned*)(g_Phi + ao);
            pal[j] = *(const unsigned*)(g_Plo + ao);
        }
        #pragma unroll
        for (int j = 0; j < 8; j++) {
            size_t bo = (size_t)(kt * 16 + bk2[j]) * H4 + n0 + bn[j];
            pbh[j] = g_WihPkHi[bo];
            pbl[j] = g_WihPkLo[bo];
        }
    };
    auto storeS = [&]() {
        #pragma unroll
        for (int j = 0; j < 8; j++) { Ah[arow[j]][ac2[j]] = pah[j]; Al[arow[j]][ac2[j]] = pal[j]; }
        #pragma unroll
        for (int j = 0; j < 8; j++) { Bh[bn[j]][bk2[j]] = pbh[j]; Bl[bn[j]][bk2[j]] = pbl[j]; }
    };
    loadG(0); storeS(); __syncthreads();
    for (int kt = 0; kt < NKT; kt++) {
        if (kt + 1 < NKT) loadG(kt + 1);
        #pragma unroll
        for (int s = 0; s < 2; s++) {
            unsigned bfh[4][2], bfl[4][2];
            #pragma unroll
            for (int nt = 0; nt < 4; nt++) {
                int n = warpN * 32 + nt * 8 + (lane >> 2);
                bfh[nt][0] = Bh[n][(lane & 3) + s * 8];
                bfh[nt][1] = Bh[n][(lane & 3) + 4 + s * 8];
                bfl[nt][0] = Bl[n][(lane & 3) + s * 8];
                bfl[nt][1] = Bl[n][(lane & 3) + 4 + s * 8];
            }
            #pragma unroll
            for (int mt = 0; mt < 4; mt++) {
                int r = warpM * 64 + mt * 16 + (lane >> 2);
                unsigned a0 = Ah[r][(lane & 3) + s * 8];
                unsigned a1 = Ah[r + 8][(lane & 3) + s * 8];
                unsigned a2 = Ah[r][(lane & 3) + 4 + s * 8];
                unsigned a3 = Ah[r + 8][(lane & 3) + 4 + s * 8];
                #pragma unroll
                for (int nt = 0; nt < 4; nt++)
                    mma16816(acc[mt][nt], a0, a1, a2, a3, bfh[nt][0], bfh[nt][1]);
                #pragma unroll
                for (int nt = 0; nt < 4; nt++)
                    mma16816(acc[mt][nt], a0, a1, a2, a3, bfl[nt][0], bfl[nt][1]);
                unsigned l0 = Al[r][(lane & 3) + s * 8];
                unsigned l1 = Al[r + 8][(lane & 3) + s * 8];
                unsigned l2 = Al[r][(lane & 3) + 4 + s * 8];
                unsigned l3 = Al[r + 8][(lane & 3) + 4 + s * 8];
                #pragma unroll
                for (int nt = 0; nt < 4; nt++)
                    mma16816(acc[mt][nt], l0, l1, l2, l3, bfh[nt][0], bfh[nt][1]);
            }
        }
        __syncthreads();
        if (kt + 1 < NKT) { storeS(); __syncthreads(); }
    }
    #pragma unroll
    for (int mt = 0; mt < 4; mt++) {
        int mrow = m0 + warpM * 64 + mt * 16 + (lane >> 2);
        #pragma unroll
        for (int half = 0; half < 2; half++) {
            int m = mrow + half * 8;
            #pragma unroll
            for (int nt = 0; nt < 4; nt++) {
                int n = n0 + warpN * 32 + nt * 8 + (lane & 3) * 2;
                g_P[(size_t)m * H4 + n]     = acc[mt][nt][half * 2]     + g_biasP[n];
                g_P[(size_t)m * H4 + n + 1] = acc[mt][nt][half * 2 + 1] + g_biasP[n + 1];
            }
        }
    }
}

// ---------------- per-step: gates = h @ Whh_p ; LSTM epilogue ---------------
__global__ __launch_bounds__(256) void step_kernel(int t)
{
    __shared__ float As[16][34];           // [k][m]
    __shared__ float Bs[16][66];           // [k][n]
    const float* hs = (t & 1) ? g_hB : g_hA;
    float* hd       = (t & 1) ? g_hA : g_hB;
    int tid = threadIdx.x;
    int n0 = blockIdx.x * 64;
    int m0 = blockIdx.y * 32;
    int ty = tid >> 4, tx = tid & 15;
    int tm = ty * 2;
    int tn = tx * 4;
    float acc[2][4] = {};
    for (int k0 = 0; k0 < H; k0 += 16) {
        #pragma unroll
        for (int i = 0; i < 2; i++) {
            int idx = tid + i * 256;
            int kk = idx >> 5, mm = idx & 31;
            As[kk][mm] = hs[(size_t)(m0 + mm) * H + k0 + kk];
        }
        #pragma unroll
        for (int i = 0; i < 4; i++) {
            int idx = tid + i * 256;
            int kk = idx >> 6, nn = idx & 63;
            Bs[kk][nn] = g_Whh_p[(size_t)(k0 + kk) * H4 + n0 + nn];
        }
        __syncthreads();
        #pragma unroll
        for (int k = 0; k < 16; k++) {
            float a0 = As[k][tm], a1 = As[k][tm + 1];
            float b0 = Bs[k][tn], b1 = Bs[k][tn + 1];
            float b2 = Bs[k][tn + 2], b3 = Bs[k][tn + 3];
            acc[0][0] += a0 * b0; acc[0][1] += a0 * b1;
            acc[0][2] += a0 * b2; acc[0][3] += a0 * b3;
            acc[1][0] += a1 * b0; acc[1][1] += a1 * b1;
            acc[1][2] += a1 * b2; acc[1][3] += a1 * b3;
        }
        __syncthreads();
    }
    int hh = (n0 + tn) >> 2;
    #pragma unroll
    for (int i = 0; i < 2; i++) {
        int m = m0 + tm + i;
        const float* Pr = g_P + (size_t)(t * B + m) * H4 + n0 + tn;
        float gi = acc[i][0] + Pr[0];
        float gf = acc[i][1] + Pr[1];
        float gg = acc[i][2] + Pr[2];
        float go = acc[i][3] + Pr[3];
        float si = fast_sig(gi);
        float sf = fast_sig(gf);
        float so = fast_sig(go);
        int idx = m * H + hh;
        float c = sf * g_c[idx] + si * fast_tanh(gg);
        float h = so * fast_tanh(c);
        g_c[idx] = c;
        hd[idx] = h;
        int xi = (t * B + m) * H2 + hh;
        g_Xhi[xi] = __float2half_rn(h);
    }
}

// ---------------- hw = h_new @ Wh : [128,512] @ [512,512] -------------------
__global__ void hw_kernel(const float* __restrict__ Wh, int t)
{
    __shared__ float As[16][18];
    __shared__ float Bs[16][66];
    const float* hsrc = (t & 1) ? g_hA : g_hB;   // NEW h written by step_kernel
    int tid = threadIdx.x;
    int n0 = blockIdx.x * 64;
    int m0 = blockIdx.y * 16;
    int r  = tid >> 4;
    int tn = (tid & 15) * 4;
    float acc[4] = {};
    for (int k0 = 0; k0 < H; k0 += 16) {
        {
            int mm = tid >> 4, kk = tid & 15;
            As[mm][kk] = hsrc[(size_t)(m0 + mm) * H + k0 + kk];
        }
        #pragma unroll
        for (int i = 0; i < 4; i++) {
            int idx = tid + i * 256;
            int kk = idx >> 6, nn = idx & 63;
            Bs[kk][nn] = Wh[(size_t)(k0 + kk) * H + n0 + nn];
        }
        __syncthreads();
        #pragma unroll
        for (int k = 0; k < 16; k++) {
            float a = As[r][k];
            acc[0] += a * Bs[k][tn];
            acc[1] += a * Bs[k][tn + 1];
            acc[2] += a * Bs[k][tn + 2];
            acc[3] += a * Bs[k][tn + 3];
        }
        __syncthreads();
    }
    #pragma unroll
    for (int j = 0; j < 4; j++)
        g_hw[(size_t)(m0 + r) * H + n0 + tn + j] = acc[j];
}

// ---------------- attention: scores, softmax, attended -> Xhi ---------------
__global__ void attn_kernel(const float* __restrict__ wo, const float* __restrict__ area, int t)
{
    int bb = blockIdx.x, tid = threadIdx.x;   // 128 blocks x 256
    __shared__ float shw[512];
    __shared__ float swo[512];
    __shared__ float sal[52];
    shw[tid]       = g_hw[(size_t)bb * H + tid];
    shw[tid + 256] = g_hw[(size_t)bb * H + tid + 256];
    swo[tid]       = wo[tid];
    swo[tid + 256] = wo[tid + 256];
    __syncthreads();
    int warp = tid >> 5, lane = tid & 31;
    for (int f = warp; f < F; f += 8) {
        const float* vp = g_Vproj + ((size_t)bb * F + f) * H;
        float s = 0.f;
        for (int k = lane; k < H; k += 32)
            s += swo[k] * fast_tanh(vp[k] + shw[k]);
        #pragma unroll
        for (int off = 16; off; off >>= 1)
            s += __shfl_xor_sync(0xffffffffu, s, off);
        if (lane == 0) sal[f] = s;
    }
    __syncthreads();
    if (tid < 32) {
        float v0 = (tid < F) ? sal[tid] : -3.4e38f;
        float v1 = (tid + 32 < F) ? sal[tid + 32] : -3.4e38f;
        float mx = fmaxf(v0, v1);
        #pragma unroll
        for (int off = 16; off; off >>= 1)
            mx = fmaxf(mx, __shfl_xor_sync(0xffffffffu, mx, off));
        float e0 = (tid < F) ? __expf(v0 - mx) : 0.f;
        float e1 = (tid + 32 < F) ? __expf(v1 - mx) : 0.f;
        float s = e0 + e1;
        #pragma unroll
        for (int off = 16; off; off >>= 1)
            s += __shfl_xor_sync(0xffffffffu, s, off);
        float inv = __fdividef(1.f, s);
        if (tid < F) sal[tid] = e0 * inv;
        if (tid + 32 < F) sal[tid + 32] = e1 * inv;
    }
    __syncthreads();
    for (int h = tid; h < H; h += 256) {
        const float* ar = area + ((size_t)bb * H + h) * F;
        float s = 0.f;
        #pragma unroll
        for (int f = 0; f < F; f++) s += ar[f] * sal[f];
        int xi = (t * B + bb) * H2 + H + h;
        g_Xhi[xi] = __float2half_rn(s);
    }
}

// ---------------- final slice: out rows of one t (fp16 single-term) ---------
__global__ __launch_bounds__(256) void final_slice_kernel(const float* __restrict__ bias,
                                                          float* __restrict__ out, int m0)
{
    __shared__ unsigned Ah[128][17];
    __shared__ unsigned Bs[128][17];
    int tid = threadIdx.x;
    int lane = tid & 31, warp = tid >> 5;
    int warpM = warp >> 2, warpN = warp & 3;
    int n0 = blockIdx.x * 128;                        // 79 blocks
    float acc[4][4][4];
    #pragma unroll
    for (int i = 0; i < 4; i++)
        #pragma unroll
        for (int j = 0; j < 4; j++)
            #pragma unroll
            for (int q = 0; q < 4; q++) acc[i][j][q] = 0.f;

    unsigned pah[8], pb[8];
    const int NKT = 32;
    int arow[8], ac2[8], bn[8], bk2[8];
    #pragma unroll
    for (int j = 0; j < 8; j++) {
        int i = tid + j * 256;
        arow[j] = i >> 4;  ac2[j] = i & 15;
        bn[j] = i & 127;   bk2[j] = i >> 7;
    }
    auto loadG = [&](int kt) {
        int kk0 = kt * 32;
        #pragma unroll
        for (int j = 0; j < 8; j++) {
            size_t ao = (size_t)(m0 + arow[j]) * H2 + kk0 + ac2[j] * 2;
            pah[j] = *(const unsigned*)(g_Xhi + ao);
        }
        #pragma unroll
        for (int j = 0; j < 8; j++)
            pb[j] = g_WoPk[(size_t)(kt * 16 + bk2[j]) * NP + n0 + bn[j]];
    };
    auto storeS = [&]() {
        #pragma unroll
        for (int j = 0; j < 8; j++) Ah[arow[j]][ac2[j]] = pah[j];
        #pragma unroll
        for (int j = 0; j < 8; j++) Bs[bn[j]][bk2[j]] = pb[j];
    };
    loadG(0); storeS(); __syncthreads();
    for (int kt = 0; kt < NKT; kt++) {
        if (kt + 1 < NKT) loadG(kt + 1);
        #pragma unroll
        for (int s = 0; s < 2; s++) {
            unsigned bf[4][2];
            #pragma unroll
            for (int nt = 0; nt < 4; nt++) {
                int n = warpN * 32 + nt * 8 + (lane >> 2);
                bf[nt][0] = Bs[n][(lane & 3) + s * 8];
                bf[nt][1] = Bs[n][(lane & 3) + 4 + s * 8];
            }
            #pragma unroll
            for (int mt = 0; mt < 4; mt++) {
                int r = warpM * 64 + mt * 16 + (lane >> 2);
                unsigned a0 = Ah[r][(lane & 3) + s * 8];
                unsigned a1 = Ah[r + 8][(lane & 3) + s * 8];
                unsigned a2 = Ah[r][(lane & 3) + 4 + s * 8];
                unsigned a3 = Ah[r + 8][(lane & 3) + 4 + s * 8];
                #pragma unroll
                for (int nt = 0; nt < 4; nt++)
                    mma16816(acc[mt][nt], a0, a1, a2, a3, bf[nt][0], bf[nt][1]);
            }
        }
        __syncthreads();
        if (kt + 1 < NKT) { storeS(); __syncthreads(); }
    }
    #pragma unroll
    for (int mt = 0; mt < 4; mt++) {
        int mrow = m0 + warpM * 64 + mt * 16 + (lane >> 2);
        #pragma unroll
        for (int half = 0; half < 2; half++) {
            int m = mrow + half * 8;
            int tt = m >> 7, bb = m & 127;
            size_t orow = ((size_t)bb * T + tt) * VV;
            #pragma unroll
            for (int nt = 0; nt < 4; nt++) {
                int n = n0 + warpN * 32 + nt * 8 + (lane & 3) * 2;
                if (n < VV)     out[orow + n]     = acc[mt][nt][half * 2]     + bias[n];
                if (n + 1 < VV) out[orow + n + 1] = acc[mt][nt][half * 2 + 1] + bias[n + 1];
            }
        }
    }
}

// ---------------- launcher (stream-forked DAG) ------------------------------
extern "C" void kernel_launch(void* const* d_in, const int* in_sizes, int n_in,
                              void* d_out, int out_size)
{
    const int*   cap  = (const int*)  d_in[0];   // [B,T] int32
    const float* gf   = (const float*)d_in[1];   // [B,H]
    const float* area = (const float*)d_in[2];   // [B,H,F]
    const float* h0   = (const float*)d_in[3];
    const float* c0   = (const float*)d_in[4];
    const float* emb  = (const float*)d_in[5];   // [V,H]
    const float* Wih  = (const float*)d_in[6];   // [2H,4H]
    const float* Whh  = (const float*)d_in[7];   // [H,4H]
    const float* bih  = (const float*)d_in[8];
    const float* bhh  = (const float*)d_in[9];
    const float* Wv   = (const float*)d_in[10];  // [H,H]
    const float* Wh   = (const float*)d_in[11];  // [H,H]
    const float* wo   = (const float*)d_in[12];  // [H]
    const float* Wout = (const float*)d_in[13];  // [2H,V]
    const float* bout = (const float*)d_in[14];  // [V]
    float* out = (float*)d_out;

    static cudaStream_t s1 = 0, s2 = 0;
    static cudaEvent_t evFork, evW, evPre, evT[T], evS1, evS2;
    static int inited = 0;
    if (!inited) {
        cudaStreamCreateWithFlags(&s1, cudaStreamNonBlocking);
        cudaStreamCreateWithFlags(&s2, cudaStreamNonBlocking);
        cudaEventCreateWithFlags(&evFork, cudaEventDisableTiming);
        cudaEventCreateWithFlags(&evW,    cudaEventDisableTiming);
        cudaEventCreateWithFlags(&evPre,  cudaEventDisableTiming);
        cudaEventCreateWithFlags(&evS1,   cudaEventDisableTiming);
        cudaEventCreateWithFlags(&evS2,   cudaEventDisableTiming);
        for (int t = 0; t < T; t++)
            cudaEventCreateWithFlags(&evT[t], cudaEventDisableTiming);
        inited = 1;
    }
    cudaStream_t s0 = 0;   // harness stream (default)

    // fork side streams off the capture stream
    cudaEventRecord(evFork, s0);
    cudaStreamWaitEvent(s1, evFork, 0);
    cudaStreamWaitEvent(s2, evFork, 0);

    // s1: W_out conversion + Vproj (independent of recurrence prolog)
    convW_kernel<<<(512 * NP) / 256, 256, 0, s1>>>(Wout);
    cudaEventRecord(evW, s1);              // slices on s2 need convW
    vproj_kernel<<<dim3(8, 98), 256, 0, s1>>>(area, Wv);
    cudaEventRecord(evPre, s1);            // attn needs vproj
    cudaStreamWaitEvent(s2, evW, 0);

    // s0: recurrence prolog
    prep_kernel<<<256, 256, 0, s0>>>(h0, c0);
    convWih_kernel<<<(512 * H4) / 256, 256, 0, s0>>>(Wih, bih, bhh);
    convWhh_kernel<<<(H * H4) / 256, 256, 0, s0>>>(Whh);
    gatherX_kernel<<<(MM * H2) / 256, 256, 0, s0>>>(cap, gf, emb);
    pgemm_kernel<<<dim3(16, 20), 256, 0, s0>>>();
    cudaStreamWaitEvent(s0, evPre, 0);     // vproj ready before attention

    // recurrence loop with final-GEMM slices overlapped on s1/s2
    for (int t = 0; t < T; t++) {
        step_kernel<<<dim3(32, 4), 256, 0, s0>>>(t);
        hw_kernel<<<dim3(8, 8), 256, 0, s0>>>(Wh, t);
        attn_kernel<<<128, 256, 0, s0>>>(wo, area, t);
        cudaEventRecord(evT[t], s0);
        cudaStream_t ss = (t & 1) ? s2 : s1;
        cudaStreamWaitEvent(ss, evT[t], 0);
        final_slice_kernel<<<79, 256, 0, ss>>>(bout, out, t * B);
    }

    // join side streams back into s0
    cudaEventRecord(evS1, s1);
    cudaEventRecord(evS2, s2);
    cudaStreamWaitEvent(s0, evS1, 0);
    cudaStreamWaitEvent(s0, evS2, 0);
}